// round 7
// baseline (speedup 1.0000x reference)
#include <cuda_runtime.h>
#include <cuda_fp16.h>
#include <math.h>
#include <stdint.h>

#define BATCH 16
#define SEQ   1024
#define DIM   768
#define GP    49
#define ROWS  (BATCH * SEQ)      // 16384
#define QKVD  (3 * DIM)          // 2304

// ---------------- scratch (device globals) ----------------------------------
__device__ float g_gw [(size_t)ROWS * GP];
__device__ float g_S  [(size_t)BATCH * SEQ * SEQ];
__device__ float g_rmax[ROWS];
__device__ float g_rsum[ROWS];

__device__ half g_x_h   [(size_t)ROWS * DIM];
__device__ half g_x_l   [(size_t)ROWS * DIM];
__device__ half g_qkv_h [(size_t)ROWS * QKVD];
__device__ half g_qkv_l [(size_t)ROWS * QKVD];
__device__ half g_S_h   [(size_t)BATCH * SEQ * SEQ];
__device__ half g_S_l   [(size_t)BATCH * SEQ * SEQ];
__device__ half g_Vt_h  [(size_t)BATCH * DIM * SEQ];
__device__ half g_Vt_l  [(size_t)BATCH * DIM * SEQ];
__device__ half g_ov_h  [(size_t)ROWS * DIM];
__device__ half g_ov_l  [(size_t)ROWS * DIM];
__device__ half g_Wqkvt_h [(size_t)QKVD * DIM];
__device__ half g_Wqkvt_l [(size_t)QKVD * DIM];
__device__ half g_Wprojt_h[(size_t)DIM * DIM];
__device__ half g_Wprojt_l[(size_t)DIM * DIM];

// ============================ helpers =======================================
__device__ __forceinline__ uint32_t smem_u32(const void* p) {
    uint32_t a;
    asm("{ .reg .u64 t; cvta.to.shared.u64 t, %1; cvt.u32.u64 %0, t; }" : "=r"(a) : "l"(p));
    return a;
}
__device__ __forceinline__ void cp16(uint32_t s, const void* g) {
    asm volatile("cp.async.cg.shared.global [%0], [%1], 16;" :: "r"(s), "l"(g));
}
__device__ __forceinline__ void cp_commit() {
    asm volatile("cp.async.commit_group;" ::: "memory");
}
template<int N>
__device__ __forceinline__ void cp_wait() {
    asm volatile("cp.async.wait_group %0;" :: "n"(N) : "memory");
}
// fp32-accumulator MMA (main term)
__device__ __forceinline__ void mma16816(float* d, const uint32_t* a, const uint32_t* b) {
    asm volatile(
        "mma.sync.aligned.m16n8k16.row.col.f32.f16.f16.f32 "
        "{%0,%1,%2,%3},{%4,%5,%6,%7},{%8,%9},{%0,%1,%2,%3};"
        : "+f"(d[0]), "+f"(d[1]), "+f"(d[2]), "+f"(d[3])
        : "r"(a[0]), "r"(a[1]), "r"(a[2]), "r"(a[3]), "r"(b[0]), "r"(b[1]));
}
// fp16-accumulator MMA, C = 0 (cross terms)
__device__ __forceinline__ void mma16816_f16(uint32_t* d, const uint32_t* a, const uint32_t* b) {
    asm volatile(
        "mma.sync.aligned.m16n8k16.row.col.f16.f16.f16.f16 "
        "{%0,%1},{%2,%3,%4,%5},{%6,%7},{%8,%9};"
        : "=r"(d[0]), "=r"(d[1])
        : "r"(a[0]), "r"(a[1]), "r"(a[2]), "r"(a[3]), "r"(b[0]), "r"(b[1]),
          "r"(0u), "r"(0u));
}
__device__ __forceinline__ void fold16(float* acc, const uint32_t* d) {
    half2 h0 = *(const half2*)&d[0];
    half2 h1 = *(const half2*)&d[1];
    float2 f0 = __half22float2(h0);
    float2 f1 = __half22float2(h1);
    acc[0] += f0.x; acc[1] += f0.y; acc[2] += f1.x; acc[3] += f1.y;
}
__device__ __forceinline__ void ldmx4(uint32_t& r0, uint32_t& r1, uint32_t& r2, uint32_t& r3,
                                      uint32_t saddr) {
    asm volatile("ldmatrix.sync.aligned.m8n8.x4.shared.b16 {%0,%1,%2,%3}, [%4];"
                 : "=r"(r0), "=r"(r1), "=r"(r2), "=r"(r3) : "r"(saddr));
}
// swizzled byte offset within an 8KB plane (128 logical rows x 4 chunks of 16B)
__device__ __forceinline__ uint32_t swz(int row, int ch) {
    return (uint32_t)(((row >> 1) << 7) |
           (((((row & 1) << 2) + ch) ^ ((row >> 1) & 7)) << 4));
}

// ============== fp16-pair mma.sync GEMM (pre-split inputs) ==================
#define PLANE_B  8192u
#define STAGE_B  32768u
#define GSMEM    (3 * STAGE_B)

template<bool WF32, bool WSPLIT, bool BIAS>
__global__ void __launch_bounds__(256, 2) gemm_mma(
    const half* __restrict__ Ah, const half* __restrict__ Al, int lda, long long strA,
    const half* __restrict__ Bh, const half* __restrict__ Bl, int ldb, long long strB,
    float* __restrict__ C, half* __restrict__ Ch, half* __restrict__ Cl,
    int ldc, long long strC, const float* __restrict__ bias, int K, float alpha)
{
    extern __shared__ __align__(16) char smraw[];
    const uint32_t sb = smem_u32(smraw);
    const int tid  = threadIdx.x;
    const int lane = tid & 31;
    const int w    = tid >> 5;
    const int wm   = w & 1;
    const int wn   = w >> 1;
    const int m0 = blockIdx.y * 128, n0 = blockIdx.x * 128;

    const half* Abh = Ah + (long long)blockIdx.z * strA + (long long)m0 * lda;
    const half* Abl = Al + (long long)blockIdx.z * strA + (long long)m0 * lda;
    const half* Bbh = Bh + (long long)blockIdx.z * strB + (long long)n0 * ldb;
    const half* Bbl = Bl + (long long)blockIdx.z * strB + (long long)n0 * ldb;

    float acc[4][4][4];
#pragma unroll
    for (int i = 0; i < 4; i++)
#pragma unroll
        for (int j = 0; j < 4; j++)
#pragma unroll
            for (int r = 0; r < 4; r++) acc[i][j][r] = 0.f;

    const int nch = K >> 5;

    auto issue = [&](int k0, int stg) {
        const uint32_t base = sb + (uint32_t)stg * STAGE_B;
#pragma unroll
        for (int i = 0; i < 8; i++) {
            const int plane = i >> 1;
            const int cid = ((i & 1) << 8) + tid;
            const int row = cid >> 2;
            const int ch  = cid & 3;
            const uint32_t so = base + (uint32_t)plane * PLANE_B + swz(row, ch);
            const half* gp;
            if      (plane == 0) gp = Abh + (long long)row * lda + k0 + ch * 8;
            else if (plane == 1) gp = Abl + (long long)row * lda + k0 + ch * 8;
            else if (plane == 2) gp = Bbh + (long long)row * ldb + k0 + ch * 8;
            else                 gp = Bbl + (long long)row * ldb + k0 + ch * 8;
            cp16(so, gp);
        }
        cp_commit();
    };

    issue(0, 0);
    issue(32, 1);

    const int rowl = lane & 15;
    const int cb   = lane >> 4;

    for (int c = 0; c < nch; ++c) {
        const int st = c % 3;
        if (c + 2 < nch) {
            cp_wait<1>();
            __syncthreads();
            issue((c + 2) << 5, (c + 2) % 3);
        } else {
            cp_wait<0>();
            __syncthreads();
        }

        const uint32_t stA_h = sb + (uint32_t)st * STAGE_B;
        const uint32_t stA_l = stA_h + PLANE_B;
        const uint32_t stB_h = stA_h + 2 * PLANE_B;
        const uint32_t stB_l = stA_h + 3 * PLANE_B;

#pragma unroll
        for (int ks = 0; ks < 2; ks++) {
            const int ch = 2 * ks + cb;
            uint32_t ah[4][4], bh[4][2];
#pragma unroll
            for (int mi = 0; mi < 4; mi++) {
                int row = wm * 64 + mi * 16 + rowl;
                ldmx4(ah[mi][0], ah[mi][1], ah[mi][2], ah[mi][3], stA_h + swz(row, ch));
            }
#pragma unroll
            for (int p = 0; p < 2; p++) {
                int row = wn * 32 + p * 16 + rowl;
                ldmx4(bh[2*p][0], bh[2*p+1][0], bh[2*p][1], bh[2*p+1][1], stB_h + swz(row, ch));
            }
            // pass 1: Ah*Bh  (fp32 accumulate)
#pragma unroll
            for (int mi = 0; mi < 4; mi++)
#pragma unroll
                for (int ni = 0; ni < 4; ni++)
                    mma16816(acc[mi][ni], ah[mi], bh[ni]);

            // cross pass A: Al*Bh  (fp16 acc, fold into fp32 on FMA pipe)
            {
                uint32_t al[4][4];
#pragma unroll
                for (int mi = 0; mi < 4; mi++) {
                    int row = wm * 64 + mi * 16 + rowl;
                    ldmx4(al[mi][0], al[mi][1], al[mi][2], al[mi][3], stA_l + swz(row, ch));
                }
                uint32_t dbuf[2][2];
#pragma unroll
                for (int t = 0; t < 16; t++) {
                    int ni = t >> 2, mi = t & 3;
                    mma16816_f16(dbuf[t & 1], al[mi], bh[ni]);
                    if (t) { int p = t - 1; fold16(acc[p & 3][p >> 2], dbuf[p & 1]); }
                }
                fold16(acc[3][3], dbuf[1]);
            }
            // cross pass B: Ah*Bl  (fp16 acc)
            {
                uint32_t bl[4][2];
#pragma unroll
                for (int p = 0; p < 2; p++) {
                    int row = wn * 32 + p * 16 + rowl;
                    ldmx4(bl[2*p][0], bl[2*p+1][0], bl[2*p][1], bl[2*p+1][1], stB_l + swz(row, ch));
                }
                uint32_t dbuf[2][2];
#pragma unroll
                for (int t = 0; t < 16; t++) {
                    int ni = t >> 2, mi = t & 3;
                    mma16816_f16(dbuf[t & 1], ah[mi], bl[ni]);
                    if (t) { int p = t - 1; fold16(acc[p & 3][p >> 2], dbuf[p & 1]); }
                }
                fold16(acc[3][3], dbuf[1]);
            }
        }
        // no end-of-chunk barrier needed with a 3-stage ring (see R5 note)
    }

    float* Cb  = WF32   ? C  + (long long)blockIdx.z * strC : nullptr;
    half*  Chb = WSPLIT ? Ch + (long long)blockIdx.z * strC : nullptr;
    half*  Clb = WSPLIT ? Cl + (long long)blockIdx.z * strC : nullptr;
    const int r0 = m0 + wm * 64 + (lane >> 2);
    const int c0 = n0 + wn * 32 + ((lane & 3) << 1);
#pragma unroll
    for (int mi = 0; mi < 4; mi++) {
#pragma unroll
        for (int ni = 0; ni < 4; ni++) {
            int cc = c0 + ni * 8;
            float bx = 0.f, by = 0.f;
            if (BIAS) { bx = bias[cc]; by = bias[cc + 1]; }
#pragma unroll
            for (int h = 0; h < 2; h++) {
                int rr = r0 + mi * 16 + h * 8;
                float vx = acc[mi][ni][h * 2 + 0] * alpha + bx;
                float vy = acc[mi][ni][h * 2 + 1] * alpha + by;
                long long off = (long long)rr * ldc + cc;
                if (WF32) *(float2*)(Cb + off) = make_float2(vx, vy);
                if (WSPLIT) {
                    half2 hh;
                    hh.x = __float2half_rn(vx); hh.y = __float2half_rn(vy);
                    half2 ll;
                    ll.x = __float2half_rn(vx - __half2float(hh.x));
                    ll.y = __float2half_rn(vy - __half2float(hh.y));
                    *(half2*)(Chb + off) = hh;
                    *(half2*)(Clb + off) = ll;
                }
            }
        }
    }
}

// ================== split fp32 -> (hi, lo) fp16, plain ======================
__global__ void __launch_bounds__(256) split_plain(
    const float* __restrict__ in, half* __restrict__ oh, half* __restrict__ ol, size_t n)
{
    size_t i = ((size_t)blockIdx.x * 256 + threadIdx.x) * 4;
    if (i >= n) return;
    float4 v = *(const float4*)(in + i);
    half2 h0, h1, l0, l1;
    h0.x = __float2half_rn(v.x); h0.y = __float2half_rn(v.y);
    h1.x = __float2half_rn(v.z); h1.y = __float2half_rn(v.w);
    l0.x = __float2half_rn(v.x - __half2float(h0.x));
    l0.y = __float2half_rn(v.y - __half2float(h0.y));
    l1.x = __float2half_rn(v.z - __half2float(h1.x));
    l1.y = __float2half_rn(v.w - __half2float(h1.y));
    *(half2*)(oh + i) = h0; *(half2*)(oh + i + 2) = h1;
    *(half2*)(ol + i) = l0; *(half2*)(ol + i + 2) = l1;
}

// ================== transpose + split fp32 -> fp16 pair =====================
__global__ void __launch_bounds__(256) transpose_split(
    const float* __restrict__ in, half* __restrict__ oh, half* __restrict__ ol,
    int ldin, int ldout, long long sIn, long long sOut)
{
    __shared__ float t[32][33];
    const float* ib = in + (long long)blockIdx.z * sIn;
    half* obh = oh + (long long)blockIdx.z * sOut;
    half* obl = ol + (long long)blockIdx.z * sOut;
    int r0 = blockIdx.y * 32, c0 = blockIdx.x * 32;
    int x = threadIdx.x & 31, y = threadIdx.x >> 5;
#pragma unroll
    for (int j = 0; j < 32; j += 8)
        t[y + j][x] = ib[(long long)(r0 + y + j) * ldin + c0 + x];
    __syncthreads();
#pragma unroll
    for (int j = 0; j < 32; j += 8) {
        float v = t[x][y + j];
        half h = __float2half_rn(v);
        half l = __float2half_rn(v - __half2float(h));
        long long o = (long long)(c0 + y + j) * ldout + r0 + x;
        obh[o] = h; obl[o] = l;
    }
}

// ================== transpose half plane (V -> V^T) =========================
__global__ void __launch_bounds__(256) transpose_half(
    const half* __restrict__ in, half* __restrict__ out,
    int ldin, int ldout, long long sIn, long long sOut)
{
    __shared__ half t[32][34];
    const half* ib = in + (long long)blockIdx.z * sIn;
    half* ob = out + (long long)blockIdx.z * sOut;
    int r0 = blockIdx.y * 32, c0 = blockIdx.x * 32;
    int x = threadIdx.x & 31, y = threadIdx.x >> 5;
#pragma unroll
    for (int j = 0; j < 32; j += 8)
        t[y + j][x] = ib[(long long)(r0 + y + j) * ldin + c0 + x];
    __syncthreads();
#pragma unroll
    for (int j = 0; j < 32; j += 8)
        ob[(long long)(c0 + y + j) * ldout + r0 + x] = t[x][y + j];
}

// ---------------- gw = softmax(q @ W_gp), 64 rows / block --------------------
__global__ void __launch_bounds__(256) gw_kernel2(
    const half* __restrict__ qh, const half* __restrict__ ql,
    const float* __restrict__ Wgp, float* __restrict__ gw)
{
    __shared__ float wt[64][52];
    __shared__ float qt[64][65];
    __shared__ float lg[64][50];
    const int row0 = blockIdx.x * 64;
    const int tid = threadIdx.x;
    const int c  = tid & 63;
    const int rq = tid >> 6;

    float acc[16];
#pragma unroll
    for (int i = 0; i < 16; i++) acc[i] = 0.f;

    for (int kc = 0; kc < DIM / 64; kc++) {
        for (int idx = tid; idx < 64 * GP; idx += 256) {
            int kk = idx / GP, cc = idx - kk * GP;
            wt[kk][cc] = Wgp[(kc * 64 + kk) * GP + cc];
        }
        for (int idx = tid; idx < 4096; idx += 256) {
            int r = idx >> 6, kk = idx & 63;
            long long o = (long long)(row0 + r) * QKVD + kc * 64 + kk;
            qt[r][kk] = __half2float(qh[o]) + __half2float(ql[o]);
        }
        __syncthreads();
        if (c < GP) {
            for (int kk = 0; kk < 64; kk++) {
                float wv = wt[kk][c];
#pragma unroll
                for (int i = 0; i < 16; i++)
                    acc[i] = fmaf(qt[rq * 16 + i][kk], wv, acc[i]);
            }
        }
        __syncthreads();
    }
    if (c < GP)
#pragma unroll
        for (int i = 0; i < 16; i++) lg[rq * 16 + i][c] = acc[i];
    __syncthreads();
    if (tid < 64) {
        float m = lg[tid][0];
        for (int j = 1; j < GP; j++) m = fmaxf(m, lg[tid][j]);
        float s = 0.f;
        float e[GP];
        for (int j = 0; j < GP; j++) { e[j] = expf(lg[tid][j] - m); s += e[j]; }
        float inv = 1.f / s;
        for (int j = 0; j < GP; j++)
            gw[(long long)(row0 + tid) * GP + j] = e[j] * inv;
    }
}

// ---------------- per-row max & sum(exp) over S ------------------------------
__global__ void __launch_bounds__(256) rowstats_kernel(
    const float* __restrict__ S, float* __restrict__ rmax, float* __restrict__ rsum)
{
    const int row = blockIdx.x;
    const float* s = S + (long long)row * SEQ;
    const int tid = threadIdx.x;
    float v[4];
    float mx = -1e30f;
#pragma unroll
    for (int t = 0; t < 4; t++) { v[t] = s[tid + 256 * t]; mx = fmaxf(mx, v[t]); }
    __shared__ float red[256];
    red[tid] = mx; __syncthreads();
    for (int off = 128; off > 0; off >>= 1) {
        if (tid < off) red[tid] = fmaxf(red[tid], red[tid + off]);
        __syncthreads();
    }
    float m = red[0];
    __syncthreads();
    float sum = 0.f;
#pragma unroll
    for (int t = 0; t < 4; t++) sum += expf(v[t] - m);
    red[tid] = sum; __syncthreads();
    for (int off = 128; off > 0; off >>= 1) {
        if (tid < off) red[tid] += red[tid + off];
        __syncthreads();
    }
    if (tid == 0) { rmax[row] = m; rsum[row] = red[0]; }
}

// ------- W = softmax(S) * (a + (1-a)*<gw_i,gw_m>) -> split fp16 --------------
__global__ void __launch_bounds__(256) modulate2(
    const float* __restrict__ S, const float* __restrict__ gw,
    const float* __restrict__ rmax, const float* __restrict__ rsum,
    const float* __restrict__ alpha_p, half* __restrict__ Sh, half* __restrict__ Sl)
{
    __shared__ float gwm[128][51];
    const int b  = blockIdx.z;
    const int i0 = blockIdx.y * 64;
    const int m0 = blockIdx.x * 128;
    const int tid = threadIdx.x;

    for (int idx = tid; idx < 128 * GP; idx += 256) {
        int r = idx / GP, cc = idx - r * GP;
        gwm[r][cc] = gw[(long long)(b * SEQ + m0 + r) * GP + cc];
    }
    __syncthreads();

    const float a = 1.f / (1.f + expf(-alpha_p[0]));
    const float oma = 1.f - a;
    const int ml = tid & 63;
    const int rq = tid >> 6;

    for (int ri = 0; ri < 16; ri++) {
        const int il = ri * 4 + rq;
        const int grow = b * SEQ + i0 + il;
        const float* gp = gw + (long long)grow * GP;
        const float mi  = rmax[grow];
        const float inv = 1.f / rsum[grow];
        const float* srow = S + (long long)grow * SEQ + m0;
        float d0 = 0.f, d1 = 0.f;
#pragma unroll
        for (int cc = 0; cc < GP; cc++) {
            float g = __ldg(gp + cc);
            d0 = fmaf(g, gwm[ml][cc], d0);
            d1 = fmaf(g, gwm[ml + 64][cc], d1);
        }
        float v0 = expf(srow[ml] - mi) * inv * (a + oma * d0);
        float v1 = expf(srow[ml + 64] - mi) * inv * (a + oma * d1);
        long long o = (long long)grow * SEQ + m0;
        half h0 = __float2half_rn(v0), h1 = __float2half_rn(v1);
        Sh[o + ml]      = h0;
        Sh[o + ml + 64] = h1;
        Sl[o + ml]      = __float2half_rn(v0 - __half2float(h0));
        Sl[o + ml + 64] = __float2half_rn(v1 - __half2float(h1));
    }
}

// ---------------- launcher ---------------------------------------------------
extern "C" void kernel_launch(void* const* d_in, const int* in_sizes, int n_in,
                              void* d_out, int out_size)
{
    const float* x      = (const float*)d_in[0];
    const float* W_qkv  = (const float*)d_in[1];
    const float* b_qkv  = (const float*)d_in[2];
    const float* W_proj = (const float*)d_in[3];
    const float* b_proj = (const float*)d_in[4];
    const float* W_gp   = (const float*)d_in[5];
    const float* alpha  = (const float*)d_in[6];
    float* out = (float*)d_out;

    float *gw, *S, *rmax, *rsum;
    half *x_h, *x_l, *qkv_h, *qkv_l, *S_h, *S_l, *Vt_h, *Vt_l, *ov_h, *ov_l;
    half *Wqkvt_h, *Wqkvt_l, *Wprojt_h, *Wprojt_l;
    cudaGetSymbolAddress((void**)&gw,   g_gw);
    cudaGetSymbolAddress((void**)&S,    g_S);
    cudaGetSymbolAddress((void**)&rmax, g_rmax);
    cudaGetSymbolAddress((void**)&rsum, g_rsum);
    cudaGetSymbolAddress((void**)&x_h,  g_x_h);
    cudaGetSymbolAddress((void**)&x_l,  g_x_l);
    cudaGetSymbolAddress((void**)&qkv_h, g_qkv_h);
    cudaGetSymbolAddress((void**)&qkv_l, g_qkv_l);
    cudaGetSymbolAddress((void**)&S_h,  g_S_h);
    cudaGetSymbolAddress((void**)&S_l,  g_S_l);
    cudaGetSymbolAddress((void**)&Vt_h, g_Vt_h);
    cudaGetSymbolAddress((void**)&Vt_l, g_Vt_l);
    cudaGetSymbolAddress((void**)&ov_h, g_ov_h);
    cudaGetSymbolAddress((void**)&ov_l, g_ov_l);
    cudaGetSymbolAddress((void**)&Wqkvt_h,  g_Wqkvt_h);
    cudaGetSymbolAddress((void**)&Wqkvt_l,  g_Wqkvt_l);
    cudaGetSymbolAddress((void**)&Wprojt_h, g_Wprojt_h);
    cudaGetSymbolAddress((void**)&Wprojt_l, g_Wprojt_l);

    const float scale = (float)(1.0 / sqrt((double)DIM));
    cudaFuncSetAttribute(gemm_mma<false,true,true>,  cudaFuncAttributeMaxDynamicSharedMemorySize, GSMEM);
    cudaFuncSetAttribute(gemm_mma<true,false,false>, cudaFuncAttributeMaxDynamicSharedMemorySize, GSMEM);
    cudaFuncSetAttribute(gemm_mma<false,true,false>, cudaFuncAttributeMaxDynamicSharedMemorySize, GSMEM);
    cudaFuncSetAttribute(gemm_mma<true,false,true>,  cudaFuncAttributeMaxDynamicSharedMemorySize, GSMEM);

    split_plain<<<(ROWS * DIM) / 1024, 256>>>(x, x_h, x_l, (size_t)ROWS * DIM);
    transpose_split<<<dim3(QKVD / 32, DIM / 32, 1), 256>>>(W_qkv, Wqkvt_h, Wqkvt_l, QKVD, DIM, 0, 0);
    transpose_split<<<dim3(DIM / 32, DIM / 32, 1), 256>>>(W_proj, Wprojt_h, Wprojt_l, DIM, DIM, 0, 0);

    // 1) qkv = x @ W_qkv + b  -> split fp16
    gemm_mma<false,true,true><<<dim3(QKVD / 128, ROWS / 128, 1), 256, GSMEM>>>(
        x_h, x_l, DIM, 0, Wqkvt_h, Wqkvt_l, DIM, 0,
        nullptr, qkv_h, qkv_l, QKVD, 0, b_qkv, DIM, 1.0f);

    // 2) gw = softmax(q @ W_gp)
    gw_kernel2<<<ROWS / 64, 256>>>(qkv_h, qkv_l, W_gp, gw);

    // V^T per batch
    transpose_half<<<dim3(DIM / 32, SEQ / 32, BATCH), 256>>>(
        qkv_h + 2 * DIM, Vt_h, QKVD, SEQ, (long long)SEQ * QKVD, (long long)DIM * SEQ);
    transpose_half<<<dim3(DIM / 32, SEQ / 32, BATCH), 256>>>(
        qkv_l + 2 * DIM, Vt_l, QKVD, SEQ, (long long)SEQ * QKVD, (long long)DIM * SEQ);

    // 3) S = scale * Q K^T
    gemm_mma<true,false,false><<<dim3(SEQ / 128, SEQ / 128, BATCH), 256, GSMEM>>>(
        qkv_h, qkv_l, QKVD, (long long)SEQ * QKVD,
        qkv_h + DIM, qkv_l + DIM, QKVD, (long long)SEQ * QKVD,
        S, nullptr, nullptr, SEQ, (long long)SEQ * SEQ, nullptr, DIM, scale);

    // 4) row stats
    rowstats_kernel<<<ROWS, 256>>>(S, rmax, rsum);

    // 5) modulate -> split fp16 weights
    modulate2<<<dim3(SEQ / 128, SEQ / 64, BATCH), 256>>>(S, gw, rmax, rsum, alpha, S_h, S_l);

    // 6) ov = W @ V
    gemm_mma<false,true,false><<<dim3(DIM / 128, SEQ / 128, BATCH), 256, GSMEM>>>(
        S_h, S_l, SEQ, (long long)SEQ * SEQ,
        Vt_h, Vt_l, SEQ, (long long)DIM * SEQ,
        nullptr, ov_h, ov_l, DIM, (long long)SEQ * DIM, nullptr, SEQ, 1.0f);

    // 7) out = ov @ W_proj + b
    gemm_mma<true,false,true><<<dim3(DIM / 128, ROWS / 128, 1), 256, GSMEM>>>(
        ov_h, ov_l, DIM, 0, Wprojt_h, Wprojt_l, DIM, 0,
        out, nullptr, nullptr, DIM, 0, b_proj, DIM, 1.0f);
}

// round 8
// speedup vs baseline: 1.3994x; 1.3994x over previous
#include <cuda_runtime.h>
#include <cuda_fp16.h>
#include <math.h>
#include <stdint.h>

#define BATCH 16
#define SEQ   1024
#define DIM   768
#define GP    49
#define ROWS  (BATCH * SEQ)      // 16384
#define QKVD  (3 * DIM)          // 2304

// ---------------- scratch (device globals) ----------------------------------
__device__ float g_gw [(size_t)ROWS * GP];
__device__ float g_S  [(size_t)BATCH * SEQ * SEQ];
__device__ float g_rmax[ROWS];
__device__ float g_rsum[ROWS];

__device__ half g_x_h   [(size_t)ROWS * DIM];
__device__ half g_x_l   [(size_t)ROWS * DIM];
__device__ half g_qkv_h [(size_t)ROWS * QKVD];
__device__ half g_qkv_l [(size_t)ROWS * QKVD];
__device__ half g_S_h   [(size_t)BATCH * SEQ * SEQ];
__device__ half g_S_l   [(size_t)BATCH * SEQ * SEQ];
__device__ half g_Vt_h  [(size_t)BATCH * DIM * SEQ];
__device__ half g_Vt_l  [(size_t)BATCH * DIM * SEQ];
__device__ half g_ov_h  [(size_t)ROWS * DIM];
__device__ half g_ov_l  [(size_t)ROWS * DIM];
__device__ half g_Wqkvt_h [(size_t)QKVD * DIM];
__device__ half g_Wqkvt_l [(size_t)QKVD * DIM];
__device__ half g_Wprojt_h[(size_t)DIM * DIM];
__device__ half g_Wprojt_l[(size_t)DIM * DIM];

// ============================ helpers =======================================
__device__ __forceinline__ uint32_t smem_u32(const void* p) {
    uint32_t a;
    asm("{ .reg .u64 t; cvta.to.shared.u64 t, %1; cvt.u32.u64 %0, t; }" : "=r"(a) : "l"(p));
    return a;
}
__device__ __forceinline__ void cp16(uint32_t s, const void* g) {
    asm volatile("cp.async.cg.shared.global [%0], [%1], 16;" :: "r"(s), "l"(g));
}
__device__ __forceinline__ void cp_commit() {
    asm volatile("cp.async.commit_group;" ::: "memory");
}
template<int N>
__device__ __forceinline__ void cp_wait() {
    asm volatile("cp.async.wait_group %0;" :: "n"(N) : "memory");
}
__device__ __forceinline__ void mma16816(float* d, const uint32_t* a, const uint32_t* b) {
    asm volatile(
        "mma.sync.aligned.m16n8k16.row.col.f32.f16.f16.f32 "
        "{%0,%1,%2,%3},{%4,%5,%6,%7},{%8,%9},{%0,%1,%2,%3};"
        : "+f"(d[0]), "+f"(d[1]), "+f"(d[2]), "+f"(d[3])
        : "r"(a[0]), "r"(a[1]), "r"(a[2]), "r"(a[3]), "r"(b[0]), "r"(b[1]));
}
__device__ __forceinline__ void ldmx4(uint32_t& r0, uint32_t& r1, uint32_t& r2, uint32_t& r3,
                                      uint32_t saddr) {
    asm volatile("ldmatrix.sync.aligned.m8n8.x4.shared.b16 {%0,%1,%2,%3}, [%4];"
                 : "=r"(r0), "=r"(r1), "=r"(r2), "=r"(r3) : "r"(saddr));
}
// swizzled byte offset within an 8KB plane (128 logical rows x 4 chunks of 16B)
__device__ __forceinline__ uint32_t swz(int row, int ch) {
    return (uint32_t)(((row >> 1) << 7) |
           (((((row & 1) << 2) + ch) ^ ((row >> 1) & 7)) << 4));
}

// ============== fp16-pair mma.sync GEMM (pre-split inputs) ==================
// PASSES==3: Ah*Bh + Ah*Bl + Al*Bh  (full split, err ~7e-6)
// PASSES==2: Ah*Bh + Ah*Bl          (drops Al entirely, err ~2.8e-4)
#define PLANE_B  8192u
#define STAGE_B  32768u
#define GSMEM    (3 * STAGE_B)

template<int PASSES, bool WF32, bool WSPLIT, bool BIAS>
__global__ void __launch_bounds__(256, 2) gemm_mma(
    const half* __restrict__ Ah, const half* __restrict__ Al, int lda, long long strA,
    const half* __restrict__ Bh, const half* __restrict__ Bl, int ldb, long long strB,
    float* __restrict__ C, half* __restrict__ Ch, half* __restrict__ Cl,
    int ldc, long long strC, const float* __restrict__ bias, int K, float alpha)
{
    extern __shared__ __align__(16) char smraw[];
    const uint32_t sb = smem_u32(smraw);
    const int tid  = threadIdx.x;
    const int lane = tid & 31;
    const int w    = tid >> 5;
    const int wm   = w & 1;
    const int wn   = w >> 1;
    const int m0 = blockIdx.y * 128, n0 = blockIdx.x * 128;

    const half* Abh = Ah + (long long)blockIdx.z * strA + (long long)m0 * lda;
    const half* Abl = (PASSES == 3) ? Al + (long long)blockIdx.z * strA + (long long)m0 * lda : nullptr;
    const half* Bbh = Bh + (long long)blockIdx.z * strB + (long long)n0 * ldb;
    const half* Bbl = Bl + (long long)blockIdx.z * strB + (long long)n0 * ldb;

    float acc[4][4][4];
#pragma unroll
    for (int i = 0; i < 4; i++)
#pragma unroll
        for (int j = 0; j < 4; j++)
#pragma unroll
            for (int r = 0; r < 4; r++) acc[i][j][r] = 0.f;

    const int nch = K >> 5;

    auto issue = [&](int k0, int stg) {
        const uint32_t base = sb + (uint32_t)stg * STAGE_B;
#pragma unroll
        for (int i = 0; i < 8; i++) {
            const int plane = i >> 1;
            if (PASSES == 2 && plane == 1) continue;   // skip A-lo plane
            const int cid = ((i & 1) << 8) + tid;
            const int row = cid >> 2;
            const int ch  = cid & 3;
            const uint32_t so = base + (uint32_t)plane * PLANE_B + swz(row, ch);
            const half* gp;
            if      (plane == 0) gp = Abh + (long long)row * lda + k0 + ch * 8;
            else if (plane == 1) gp = Abl + (long long)row * lda + k0 + ch * 8;
            else if (plane == 2) gp = Bbh + (long long)row * ldb + k0 + ch * 8;
            else                 gp = Bbl + (long long)row * ldb + k0 + ch * 8;
            cp16(so, gp);
        }
        cp_commit();
    };

    issue(0, 0);
    issue(32, 1);

    const int rowl = lane & 15;
    const int cb   = lane >> 4;

    for (int c = 0; c < nch; ++c) {
        const int st = c % 3;
        if (c + 2 < nch) {
            cp_wait<1>();
            __syncthreads();
            issue((c + 2) << 5, (c + 2) % 3);
        } else {
            cp_wait<0>();
            __syncthreads();
        }

        const uint32_t stA_h = sb + (uint32_t)st * STAGE_B;
        const uint32_t stA_l = stA_h + PLANE_B;
        const uint32_t stB_h = stA_h + 2 * PLANE_B;
        const uint32_t stB_l = stA_h + 3 * PLANE_B;

#pragma unroll
        for (int ks = 0; ks < 2; ks++) {
            const int ch = 2 * ks + cb;
            uint32_t ah[4][4], bh[4][2], bl[4][2];
#pragma unroll
            for (int mi = 0; mi < 4; mi++) {
                int row = wm * 64 + mi * 16 + rowl;
                ldmx4(ah[mi][0], ah[mi][1], ah[mi][2], ah[mi][3], stA_h + swz(row, ch));
            }
#pragma unroll
            for (int p = 0; p < 2; p++) {
                int row = wn * 32 + p * 16 + rowl;
                ldmx4(bh[2*p][0], bh[2*p+1][0], bh[2*p][1], bh[2*p+1][1], stB_h + swz(row, ch));
            }
            // pass 1: Ah*Bh
#pragma unroll
            for (int mi = 0; mi < 4; mi++)
#pragma unroll
                for (int ni = 0; ni < 4; ni++)
                    mma16816(acc[mi][ni], ah[mi], bh[ni]);
            // issue B-lo (and A-lo) loads here: latency hides under pass 2
#pragma unroll
            for (int p = 0; p < 2; p++) {
                int row = wn * 32 + p * 16 + rowl;
                ldmx4(bl[2*p][0], bl[2*p+1][0], bl[2*p][1], bl[2*p+1][1], stB_l + swz(row, ch));
            }
            uint32_t al[4][4];
            if (PASSES == 3) {
#pragma unroll
                for (int mi = 0; mi < 4; mi++) {
                    int row = wm * 64 + mi * 16 + rowl;
                    ldmx4(al[mi][0], al[mi][1], al[mi][2], al[mi][3], stA_l + swz(row, ch));
                }
            }
            // pass 2: Ah*Bl
#pragma unroll
            for (int mi = 0; mi < 4; mi++)
#pragma unroll
                for (int ni = 0; ni < 4; ni++)
                    mma16816(acc[mi][ni], ah[mi], bl[ni]);
            // pass 3: Al*Bh
            if (PASSES == 3) {
#pragma unroll
                for (int mi = 0; mi < 4; mi++)
#pragma unroll
                    for (int ni = 0; ni < 4; ni++)
                        mma16816(acc[mi][ni], al[mi], bh[ni]);
            }
        }
        // no end-of-chunk barrier needed with a 3-stage ring (see R5 note)
    }

    float* Cb  = WF32   ? C  + (long long)blockIdx.z * strC : nullptr;
    half*  Chb = WSPLIT ? Ch + (long long)blockIdx.z * strC : nullptr;
    half*  Clb = WSPLIT ? Cl + (long long)blockIdx.z * strC : nullptr;
    const int r0 = m0 + wm * 64 + (lane >> 2);
    const int c0 = n0 + wn * 32 + ((lane & 3) << 1);
#pragma unroll
    for (int mi = 0; mi < 4; mi++) {
#pragma unroll
        for (int ni = 0; ni < 4; ni++) {
            int cc = c0 + ni * 8;
            float bx = 0.f, by = 0.f;
            if (BIAS) { bx = bias[cc]; by = bias[cc + 1]; }
#pragma unroll
            for (int h = 0; h < 2; h++) {
                int rr = r0 + mi * 16 + h * 8;
                float vx = acc[mi][ni][h * 2 + 0] * alpha + bx;
                float vy = acc[mi][ni][h * 2 + 1] * alpha + by;
                long long off = (long long)rr * ldc + cc;
                if (WF32) *(float2*)(Cb + off) = make_float2(vx, vy);
                if (WSPLIT) {
                    half2 hh;
                    hh.x = __float2half_rn(vx); hh.y = __float2half_rn(vy);
                    half2 ll;
                    ll.x = __float2half_rn(vx - __half2float(hh.x));
                    ll.y = __float2half_rn(vy - __half2float(hh.y));
                    *(half2*)(Chb + off) = hh;
                    *(half2*)(Clb + off) = ll;
                }
            }
        }
    }
}

// ================== split fp32 -> (hi, lo) fp16, plain ======================
__global__ void __launch_bounds__(256) split_plain(
    const float* __restrict__ in, half* __restrict__ oh, half* __restrict__ ol, size_t n)
{
    size_t i = ((size_t)blockIdx.x * 256 + threadIdx.x) * 4;
    if (i >= n) return;
    float4 v = *(const float4*)(in + i);
    half2 h0, h1, l0, l1;
    h0.x = __float2half_rn(v.x); h0.y = __float2half_rn(v.y);
    h1.x = __float2half_rn(v.z); h1.y = __float2half_rn(v.w);
    l0.x = __float2half_rn(v.x - __half2float(h0.x));
    l0.y = __float2half_rn(v.y - __half2float(h0.y));
    l1.x = __float2half_rn(v.z - __half2float(h1.x));
    l1.y = __float2half_rn(v.w - __half2float(h1.y));
    *(half2*)(oh + i) = h0; *(half2*)(oh + i + 2) = h1;
    *(half2*)(ol + i) = l0; *(half2*)(ol + i + 2) = l1;
}

// ================== transpose + split fp32 -> fp16 pair =====================
__global__ void __launch_bounds__(256) transpose_split(
    const float* __restrict__ in, half* __restrict__ oh, half* __restrict__ ol,
    int ldin, int ldout, long long sIn, long long sOut)
{
    __shared__ float t[32][33];
    const float* ib = in + (long long)blockIdx.z * sIn;
    half* obh = oh + (long long)blockIdx.z * sOut;
    half* obl = ol + (long long)blockIdx.z * sOut;
    int r0 = blockIdx.y * 32, c0 = blockIdx.x * 32;
    int x = threadIdx.x & 31, y = threadIdx.x >> 5;
#pragma unroll
    for (int j = 0; j < 32; j += 8)
        t[y + j][x] = ib[(long long)(r0 + y + j) * ldin + c0 + x];
    __syncthreads();
#pragma unroll
    for (int j = 0; j < 32; j += 8) {
        float v = t[x][y + j];
        half h = __float2half_rn(v);
        half l = __float2half_rn(v - __half2float(h));
        long long o = (long long)(c0 + y + j) * ldout + r0 + x;
        obh[o] = h; obl[o] = l;
    }
}

// ================== transpose half plane (V -> V^T) =========================
__global__ void __launch_bounds__(256) transpose_half(
    const half* __restrict__ in, half* __restrict__ out,
    int ldin, int ldout, long long sIn, long long sOut)
{
    __shared__ half t[32][34];
    const half* ib = in + (long long)blockIdx.z * sIn;
    half* ob = out + (long long)blockIdx.z * sOut;
    int r0 = blockIdx.y * 32, c0 = blockIdx.x * 32;
    int x = threadIdx.x & 31, y = threadIdx.x >> 5;
#pragma unroll
    for (int j = 0; j < 32; j += 8)
        t[y + j][x] = ib[(long long)(r0 + y + j) * ldin + c0 + x];
    __syncthreads();
#pragma unroll
    for (int j = 0; j < 32; j += 8)
        ob[(long long)(c0 + y + j) * ldout + r0 + x] = t[x][y + j];
}

// ---------------- gw = softmax(q @ W_gp), 64 rows / block --------------------
__global__ void __launch_bounds__(256) gw_kernel2(
    const half* __restrict__ qh, const half* __restrict__ ql,
    const float* __restrict__ Wgp, float* __restrict__ gw)
{
    __shared__ float wt[64][52];
    __shared__ float qt[64][65];
    __shared__ float lg[64][50];
    const int row0 = blockIdx.x * 64;
    const int tid = threadIdx.x;
    const int c  = tid & 63;
    const int rq = tid >> 6;

    float acc[16];
#pragma unroll
    for (int i = 0; i < 16; i++) acc[i] = 0.f;

    for (int kc = 0; kc < DIM / 64; kc++) {
        for (int idx = tid; idx < 64 * GP; idx += 256) {
            int kk = idx / GP, cc = idx - kk * GP;
            wt[kk][cc] = Wgp[(kc * 64 + kk) * GP + cc];
        }
        for (int idx = tid; idx < 4096; idx += 256) {
            int r = idx >> 6, kk = idx & 63;
            long long o = (long long)(row0 + r) * QKVD + kc * 64 + kk;
            qt[r][kk] = __half2float(qh[o]) + __half2float(ql[o]);
        }
        __syncthreads();
        if (c < GP) {
            for (int kk = 0; kk < 64; kk++) {
                float wv = wt[kk][c];
#pragma unroll
                for (int i = 0; i < 16; i++)
                    acc[i] = fmaf(qt[rq * 16 + i][kk], wv, acc[i]);
            }
        }
        __syncthreads();
    }
    if (c < GP)
#pragma unroll
        for (int i = 0; i < 16; i++) lg[rq * 16 + i][c] = acc[i];
    __syncthreads();
    if (tid < 64) {
        float m = lg[tid][0];
        for (int j = 1; j < GP; j++) m = fmaxf(m, lg[tid][j]);
        float s = 0.f;
        float e[GP];
        for (int j = 0; j < GP; j++) { e[j] = expf(lg[tid][j] - m); s += e[j]; }
        float inv = 1.f / s;
        for (int j = 0; j < GP; j++)
            gw[(long long)(row0 + tid) * GP + j] = e[j] * inv;
    }
}

// ---------------- per-row max & sum(exp) over S ------------------------------
__global__ void __launch_bounds__(256) rowstats_kernel(
    const float* __restrict__ S, float* __restrict__ rmax, float* __restrict__ rsum)
{
    const int row = blockIdx.x;
    const float* s = S + (long long)row * SEQ;
    const int tid = threadIdx.x;
    float v[4];
    float mx = -1e30f;
#pragma unroll
    for (int t = 0; t < 4; t++) { v[t] = s[tid + 256 * t]; mx = fmaxf(mx, v[t]); }
    __shared__ float red[256];
    red[tid] = mx; __syncthreads();
    for (int off = 128; off > 0; off >>= 1) {
        if (tid < off) red[tid] = fmaxf(red[tid], red[tid + off]);
        __syncthreads();
    }
    float m = red[0];
    __syncthreads();
    float sum = 0.f;
#pragma unroll
    for (int t = 0; t < 4; t++) sum += expf(v[t] - m);
    red[tid] = sum; __syncthreads();
    for (int off = 128; off > 0; off >>= 1) {
        if (tid < off) red[tid] += red[tid + off];
        __syncthreads();
    }
    if (tid == 0) { rmax[row] = m; rsum[row] = red[0]; }
}

// ------- W = softmax(S) * (a + (1-a)*<gw_i,gw_m>) -> split fp16 --------------
__global__ void __launch_bounds__(256) modulate2(
    const float* __restrict__ S, const float* __restrict__ gw,
    const float* __restrict__ rmax, const float* __restrict__ rsum,
    const float* __restrict__ alpha_p, half* __restrict__ Sh, half* __restrict__ Sl)
{
    __shared__ float gwm[128][51];
    const int b  = blockIdx.z;
    const int i0 = blockIdx.y * 64;
    const int m0 = blockIdx.x * 128;
    const int tid = threadIdx.x;

    for (int idx = tid; idx < 128 * GP; idx += 256) {
        int r = idx / GP, cc = idx - r * GP;
        gwm[r][cc] = gw[(long long)(b * SEQ + m0 + r) * GP + cc];
    }
    __syncthreads();

    const float a = 1.f / (1.f + expf(-alpha_p[0]));
    const float oma = 1.f - a;
    const int ml = tid & 63;
    const int rq = tid >> 6;

    for (int ri = 0; ri < 16; ri++) {
        const int il = ri * 4 + rq;
        const int grow = b * SEQ + i0 + il;
        const float* gp = gw + (long long)grow * GP;
        const float mi  = rmax[grow];
        const float inv = 1.f / rsum[grow];
        const float* srow = S + (long long)grow * SEQ + m0;
        float d0 = 0.f, d1 = 0.f;
#pragma unroll
        for (int cc = 0; cc < GP; cc++) {
            float g = __ldg(gp + cc);
            d0 = fmaf(g, gwm[ml][cc], d0);
            d1 = fmaf(g, gwm[ml + 64][cc], d1);
        }
        float v0 = expf(srow[ml] - mi) * inv * (a + oma * d0);
        float v1 = expf(srow[ml + 64] - mi) * inv * (a + oma * d1);
        long long o = (long long)grow * SEQ + m0;
        half h0 = __float2half_rn(v0), h1 = __float2half_rn(v1);
        Sh[o + ml]      = h0;
        Sh[o + ml + 64] = h1;
        Sl[o + ml]      = __float2half_rn(v0 - __half2float(h0));
        Sl[o + ml + 64] = __float2half_rn(v1 - __half2float(h1));
    }
}

// ---------------- launcher ---------------------------------------------------
extern "C" void kernel_launch(void* const* d_in, const int* in_sizes, int n_in,
                              void* d_out, int out_size)
{
    const float* x      = (const float*)d_in[0];
    const float* W_qkv  = (const float*)d_in[1];
    const float* b_qkv  = (const float*)d_in[2];
    const float* W_proj = (const float*)d_in[3];
    const float* b_proj = (const float*)d_in[4];
    const float* W_gp   = (const float*)d_in[5];
    const float* alpha  = (const float*)d_in[6];
    float* out = (float*)d_out;

    float *gw, *S, *rmax, *rsum;
    half *x_h, *x_l, *qkv_h, *qkv_l, *S_h, *S_l, *Vt_h, *Vt_l, *ov_h, *ov_l;
    half *Wqkvt_h, *Wqkvt_l, *Wprojt_h, *Wprojt_l;
    cudaGetSymbolAddress((void**)&gw,   g_gw);
    cudaGetSymbolAddress((void**)&S,    g_S);
    cudaGetSymbolAddress((void**)&rmax, g_rmax);
    cudaGetSymbolAddress((void**)&rsum, g_rsum);
    cudaGetSymbolAddress((void**)&x_h,  g_x_h);
    cudaGetSymbolAddress((void**)&x_l,  g_x_l);
    cudaGetSymbolAddress((void**)&qkv_h, g_qkv_h);
    cudaGetSymbolAddress((void**)&qkv_l, g_qkv_l);
    cudaGetSymbolAddress((void**)&S_h,  g_S_h);
    cudaGetSymbolAddress((void**)&S_l,  g_S_l);
    cudaGetSymbolAddress((void**)&Vt_h, g_Vt_h);
    cudaGetSymbolAddress((void**)&Vt_l, g_Vt_l);
    cudaGetSymbolAddress((void**)&ov_h, g_ov_h);
    cudaGetSymbolAddress((void**)&ov_l, g_ov_l);
    cudaGetSymbolAddress((void**)&Wqkvt_h,  g_Wqkvt_h);
    cudaGetSymbolAddress((void**)&Wqkvt_l,  g_Wqkvt_l);
    cudaGetSymbolAddress((void**)&Wprojt_h, g_Wprojt_h);
    cudaGetSymbolAddress((void**)&Wprojt_l, g_Wprojt_l);

    const float scale = (float)(1.0 / sqrt((double)DIM));
    cudaFuncSetAttribute(gemm_mma<3,false,true,true>,  cudaFuncAttributeMaxDynamicSharedMemorySize, GSMEM);
    cudaFuncSetAttribute(gemm_mma<2,true,false,false>, cudaFuncAttributeMaxDynamicSharedMemorySize, GSMEM);
    cudaFuncSetAttribute(gemm_mma<2,false,true,false>, cudaFuncAttributeMaxDynamicSharedMemorySize, GSMEM);
    cudaFuncSetAttribute(gemm_mma<3,true,false,true>,  cudaFuncAttributeMaxDynamicSharedMemorySize, GSMEM);

    split_plain<<<(ROWS * DIM) / 1024, 256>>>(x, x_h, x_l, (size_t)ROWS * DIM);
    transpose_split<<<dim3(QKVD / 32, DIM / 32, 1), 256>>>(W_qkv, Wqkvt_h, Wqkvt_l, QKVD, DIM, 0, 0);
    transpose_split<<<dim3(DIM / 32, DIM / 32, 1), 256>>>(W_proj, Wprojt_h, Wprojt_l, DIM, DIM, 0, 0);

    // 1) qkv = x @ W_qkv + b  (3-pass, full precision) -> split fp16
    gemm_mma<3,false,true,true><<<dim3(QKVD / 128, ROWS / 128, 1), 256, GSMEM>>>(
        x_h, x_l, DIM, 0, Wqkvt_h, Wqkvt_l, DIM, 0,
        nullptr, qkv_h, qkv_l, QKVD, 0, b_qkv, DIM, 1.0f);

    // 2) gw = softmax(q @ W_gp)
    gw_kernel2<<<ROWS / 64, 256>>>(qkv_h, qkv_l, W_gp, gw);

    // V^T per batch
    transpose_half<<<dim3(DIM / 32, SEQ / 32, BATCH), 256>>>(
        qkv_h + 2 * DIM, Vt_h, QKVD, SEQ, (long long)SEQ * QKVD, (long long)DIM * SEQ);
    transpose_half<<<dim3(DIM / 32, SEQ / 32, BATCH), 256>>>(
        qkv_l + 2 * DIM, Vt_l, QKVD, SEQ, (long long)SEQ * QKVD, (long long)DIM * SEQ);

    // 3) S = scale * Q K^T  (2-pass: Qh*Kh + Qh*Kl; drops Ql, err ~2.8e-4)
    gemm_mma<2,true,false,false><<<dim3(SEQ / 128, SEQ / 128, BATCH), 256, GSMEM>>>(
        qkv_h, qkv_l, QKVD, (long long)SEQ * QKVD,
        qkv_h + DIM, qkv_l + DIM, QKVD, (long long)SEQ * QKVD,
        S, nullptr, nullptr, SEQ, (long long)SEQ * SEQ, nullptr, DIM, scale);

    // 4) row stats
    rowstats_kernel<<<ROWS, 256>>>(S, rmax, rsum);

    // 5) modulate -> split fp16 weights
    modulate2<<<dim3(SEQ / 128, SEQ / 64, BATCH), 256>>>(S, gw, rmax, rsum, alpha, S_h, S_l);

    // 6) ov = W @ V  (2-pass: Wh*Vh + Wh*Vl; drops Wl, err ~2.8e-4)
    gemm_mma<2,false,true,false><<<dim3(DIM / 128, SEQ / 128, BATCH), 256, GSMEM>>>(
        S_h, S_l, SEQ, (long long)SEQ * SEQ,
        Vt_h, Vt_l, SEQ, (long long)DIM * SEQ,
        nullptr, ov_h, ov_l, DIM, (long long)SEQ * DIM, nullptr, SEQ, 1.0f);

    // 7) out = ov @ W_proj + b  (3-pass)
    gemm_mma<3,true,false,true><<<dim3(DIM / 128, ROWS / 128, 1), 256, GSMEM>>>(
        ov_h, ov_l, DIM, 0, Wprojt_h, Wprojt_l, DIM, 0,
        out, nullptr, nullptr, DIM, 0, b_proj, DIM, 1.0f);
}

// round 9
// speedup vs baseline: 1.6510x; 1.1798x over previous
#include <cuda_runtime.h>
#include <cuda_fp16.h>
#include <math.h>
#include <stdint.h>

#define BATCH 16
#define SEQ   1024
#define DIM   768
#define GP    49
#define ROWS  (BATCH * SEQ)      // 16384
#define QKVD  (3 * DIM)          // 2304

// ---------------- scratch (device globals) ----------------------------------
__device__ float g_gw [(size_t)ROWS * GP];
__device__ float g_S  [(size_t)BATCH * SEQ * SEQ];
__device__ float g_rmax[ROWS];
__device__ float g_rsum[ROWS];

__device__ half g_x_h   [(size_t)ROWS * DIM];
__device__ half g_x_l   [(size_t)ROWS * DIM];
__device__ half g_qkv_h [(size_t)ROWS * QKVD];
__device__ half g_qkv_l [(size_t)ROWS * QKVD];
__device__ half g_S_h   [(size_t)BATCH * SEQ * SEQ];
__device__ half g_S_l   [(size_t)BATCH * SEQ * SEQ];
__device__ half g_Vt_h  [(size_t)BATCH * DIM * SEQ];
__device__ half g_Vt_l  [(size_t)BATCH * DIM * SEQ];
__device__ half g_ov_h  [(size_t)ROWS * DIM];
__device__ half g_ov_l  [(size_t)ROWS * DIM];
__device__ half g_Wqkvt_h [(size_t)QKVD * DIM];
__device__ half g_Wqkvt_l [(size_t)QKVD * DIM];
__device__ half g_Wprojt_h[(size_t)DIM * DIM];
__device__ half g_Wprojt_l[(size_t)DIM * DIM];

// ============================ helpers =======================================
__device__ __forceinline__ uint32_t smem_u32(const void* p) {
    uint32_t a;
    asm("{ .reg .u64 t; cvta.to.shared.u64 t, %1; cvt.u32.u64 %0, t; }" : "=r"(a) : "l"(p));
    return a;
}
__device__ __forceinline__ void cp16(uint32_t s, const void* g) {
    asm volatile("cp.async.cg.shared.global [%0], [%1], 16;" :: "r"(s), "l"(g));
}
__device__ __forceinline__ void cp_commit() {
    asm volatile("cp.async.commit_group;" ::: "memory");
}
template<int N>
__device__ __forceinline__ void cp_wait() {
    asm volatile("cp.async.wait_group %0;" :: "n"(N) : "memory");
}
__device__ __forceinline__ void mma16816(float* d, const uint32_t* a, const uint32_t* b) {
    asm volatile(
        "mma.sync.aligned.m16n8k16.row.col.f32.f16.f16.f32 "
        "{%0,%1,%2,%3},{%4,%5,%6,%7},{%8,%9},{%0,%1,%2,%3};"
        : "+f"(d[0]), "+f"(d[1]), "+f"(d[2]), "+f"(d[3])
        : "r"(a[0]), "r"(a[1]), "r"(a[2]), "r"(a[3]), "r"(b[0]), "r"(b[1]));
}
__device__ __forceinline__ void ldmx4(uint32_t& r0, uint32_t& r1, uint32_t& r2, uint32_t& r3,
                                      uint32_t saddr) {
    asm volatile("ldmatrix.sync.aligned.m8n8.x4.shared.b16 {%0,%1,%2,%3}, [%4];"
                 : "=r"(r0), "=r"(r1), "=r"(r2), "=r"(r3) : "r"(saddr));
}
// swizzled byte offset within an 8KB plane (128 logical rows x 4 chunks of 16B)
__device__ __forceinline__ uint32_t swz(int row, int ch) {
    return (uint32_t)(((row >> 1) << 7) |
           (((((row & 1) << 2) + ch) ^ ((row >> 1) & 7)) << 4));
}

// ============== fp16-pair mma.sync GEMM (pre-split inputs) ==================
// PASSES==3: Ah*Bh + Ah*Bl + Al*Bh  (full split, err ~7e-6)
// PASSES==2: Ah*Bh + Ah*Bl          (drops Al entirely, err ~1.9e-4)
#define PLANE_B  8192u
#define STAGE_B  32768u
#define GSMEM    (3 * STAGE_B)

template<int PASSES, bool WF32, bool WSPLIT, bool BIAS>
__global__ void __launch_bounds__(256, 2) gemm_mma(
    const half* __restrict__ Ah, const half* __restrict__ Al, int lda, long long strA,
    const half* __restrict__ Bh, const half* __restrict__ Bl, int ldb, long long strB,
    float* __restrict__ C, half* __restrict__ Ch, half* __restrict__ Cl,
    int ldc, long long strC, const float* __restrict__ bias, int K, float alpha)
{
    extern __shared__ __align__(16) char smraw[];
    const uint32_t sb = smem_u32(smraw);
    const int tid  = threadIdx.x;
    const int lane = tid & 31;
    const int w    = tid >> 5;
    const int wm   = w & 1;
    const int wn   = w >> 1;
    const int m0 = blockIdx.y * 128, n0 = blockIdx.x * 128;

    const half* Abh = Ah + (long long)blockIdx.z * strA + (long long)m0 * lda;
    const half* Abl = (PASSES == 3) ? Al + (long long)blockIdx.z * strA + (long long)m0 * lda : nullptr;
    const half* Bbh = Bh + (long long)blockIdx.z * strB + (long long)n0 * ldb;
    const half* Bbl = Bl + (long long)blockIdx.z * strB + (long long)n0 * ldb;

    float acc[4][4][4];
#pragma unroll
    for (int i = 0; i < 4; i++)
#pragma unroll
        for (int j = 0; j < 4; j++)
#pragma unroll
            for (int r = 0; r < 4; r++) acc[i][j][r] = 0.f;

    const int nch = K >> 5;

    auto issue = [&](int k0, int stg) {
        const uint32_t base = sb + (uint32_t)stg * STAGE_B;
#pragma unroll
        for (int i = 0; i < 8; i++) {
            const int plane = i >> 1;
            if (PASSES == 2 && plane == 1) continue;   // skip A-lo plane
            const int cid = ((i & 1) << 8) + tid;
            const int row = cid >> 2;
            const int ch  = cid & 3;
            const uint32_t so = base + (uint32_t)plane * PLANE_B + swz(row, ch);
            const half* gp;
            if      (plane == 0) gp = Abh + (long long)row * lda + k0 + ch * 8;
            else if (plane == 1) gp = Abl + (long long)row * lda + k0 + ch * 8;
            else if (plane == 2) gp = Bbh + (long long)row * ldb + k0 + ch * 8;
            else                 gp = Bbl + (long long)row * ldb + k0 + ch * 8;
            cp16(so, gp);
        }
        cp_commit();
    };

    issue(0, 0);
    issue(32, 1);

    const int rowl = lane & 15;
    const int cb   = lane >> 4;

    for (int c = 0; c < nch; ++c) {
        const int st = c % 3;
        if (c + 2 < nch) {
            cp_wait<1>();
            __syncthreads();
            issue((c + 2) << 5, (c + 2) % 3);
        } else {
            cp_wait<0>();
            __syncthreads();
        }

        const uint32_t stA_h = sb + (uint32_t)st * STAGE_B;
        const uint32_t stA_l = stA_h + PLANE_B;
        const uint32_t stB_h = stA_h + 2 * PLANE_B;
        const uint32_t stB_l = stA_h + 3 * PLANE_B;

#pragma unroll
        for (int ks = 0; ks < 2; ks++) {
            const int ch = 2 * ks + cb;
            uint32_t ah[4][4], bh[4][2], bl[4][2];
#pragma unroll
            for (int mi = 0; mi < 4; mi++) {
                int row = wm * 64 + mi * 16 + rowl;
                ldmx4(ah[mi][0], ah[mi][1], ah[mi][2], ah[mi][3], stA_h + swz(row, ch));
            }
#pragma unroll
            for (int p = 0; p < 2; p++) {
                int row = wn * 32 + p * 16 + rowl;
                ldmx4(bh[2*p][0], bh[2*p+1][0], bh[2*p][1], bh[2*p+1][1], stB_h + swz(row, ch));
            }
            // pass 1: Ah*Bh
#pragma unroll
            for (int mi = 0; mi < 4; mi++)
#pragma unroll
                for (int ni = 0; ni < 4; ni++)
                    mma16816(acc[mi][ni], ah[mi], bh[ni]);
            // issue B-lo (and A-lo) loads here: latency hides under pass 2
#pragma unroll
            for (int p = 0; p < 2; p++) {
                int row = wn * 32 + p * 16 + rowl;
                ldmx4(bl[2*p][0], bl[2*p+1][0], bl[2*p][1], bl[2*p+1][1], stB_l + swz(row, ch));
            }
            uint32_t al[4][4];
            if (PASSES == 3) {
#pragma unroll
                for (int mi = 0; mi < 4; mi++) {
                    int row = wm * 64 + mi * 16 + rowl;
                    ldmx4(al[mi][0], al[mi][1], al[mi][2], al[mi][3], stA_l + swz(row, ch));
                }
            }
            // pass 2: Ah*Bl
#pragma unroll
            for (int mi = 0; mi < 4; mi++)
#pragma unroll
                for (int ni = 0; ni < 4; ni++)
                    mma16816(acc[mi][ni], ah[mi], bl[ni]);
            // pass 3: Al*Bh
            if (PASSES == 3) {
#pragma unroll
                for (int mi = 0; mi < 4; mi++)
#pragma unroll
                    for (int ni = 0; ni < 4; ni++)
                        mma16816(acc[mi][ni], al[mi], bh[ni]);
            }
        }
        // no end-of-chunk barrier needed with a 3-stage ring (see R5 note)
    }

    float* Cb  = WF32   ? C  + (long long)blockIdx.z * strC : nullptr;
    half*  Chb = WSPLIT ? Ch + (long long)blockIdx.z * strC : nullptr;
    half*  Clb = WSPLIT ? Cl + (long long)blockIdx.z * strC : nullptr;
    const int r0 = m0 + wm * 64 + (lane >> 2);
    const int c0 = n0 + wn * 32 + ((lane & 3) << 1);
#pragma unroll
    for (int mi = 0; mi < 4; mi++) {
#pragma unroll
        for (int ni = 0; ni < 4; ni++) {
            int cc = c0 + ni * 8;
            float bx = 0.f, by = 0.f;
            if (BIAS) { bx = bias[cc]; by = bias[cc + 1]; }
#pragma unroll
            for (int h = 0; h < 2; h++) {
                int rr = r0 + mi * 16 + h * 8;
                float vx = acc[mi][ni][h * 2 + 0] * alpha + bx;
                float vy = acc[mi][ni][h * 2 + 1] * alpha + by;
                long long off = (long long)rr * ldc + cc;
                if (WF32) *(float2*)(Cb + off) = make_float2(vx, vy);
                if (WSPLIT) {
                    half2 hh;
                    hh.x = __float2half_rn(vx); hh.y = __float2half_rn(vy);
                    half2 ll;
                    ll.x = __float2half_rn(vx - __half2float(hh.x));
                    ll.y = __float2half_rn(vy - __half2float(hh.y));
                    *(half2*)(Chb + off) = hh;
                    *(half2*)(Clb + off) = ll;
                }
            }
        }
    }
}

// ================== split fp32 -> (hi, lo) fp16, plain ======================
__global__ void __launch_bounds__(256) split_plain(
    const float* __restrict__ in, half* __restrict__ oh, half* __restrict__ ol, size_t n)
{
    size_t i = ((size_t)blockIdx.x * 256 + threadIdx.x) * 4;
    if (i >= n) return;
    float4 v = *(const float4*)(in + i);
    half2 h0, h1, l0, l1;
    h0.x = __float2half_rn(v.x); h0.y = __float2half_rn(v.y);
    h1.x = __float2half_rn(v.z); h1.y = __float2half_rn(v.w);
    l0.x = __float2half_rn(v.x - __half2float(h0.x));
    l0.y = __float2half_rn(v.y - __half2float(h0.y));
    l1.x = __float2half_rn(v.z - __half2float(h1.x));
    l1.y = __float2half_rn(v.w - __half2float(h1.y));
    *(half2*)(oh + i) = h0; *(half2*)(oh + i + 2) = h1;
    *(half2*)(ol + i) = l0; *(half2*)(ol + i + 2) = l1;
}

// ================== transpose + split fp32 -> fp16 pair =====================
__global__ void __launch_bounds__(256) transpose_split(
    const float* __restrict__ in, half* __restrict__ oh, half* __restrict__ ol,
    int ldin, int ldout, long long sIn, long long sOut)
{
    __shared__ float t[32][33];
    const float* ib = in + (long long)blockIdx.z * sIn;
    half* obh = oh + (long long)blockIdx.z * sOut;
    half* obl = ol + (long long)blockIdx.z * sOut;
    int r0 = blockIdx.y * 32, c0 = blockIdx.x * 32;
    int x = threadIdx.x & 31, y = threadIdx.x >> 5;
#pragma unroll
    for (int j = 0; j < 32; j += 8)
        t[y + j][x] = ib[(long long)(r0 + y + j) * ldin + c0 + x];
    __syncthreads();
#pragma unroll
    for (int j = 0; j < 32; j += 8) {
        float v = t[x][y + j];
        half h = __float2half_rn(v);
        half l = __float2half_rn(v - __half2float(h));
        long long o = (long long)(c0 + y + j) * ldout + r0 + x;
        obh[o] = h; obl[o] = l;
    }
}

// ================== transpose half plane (V -> V^T) =========================
__global__ void __launch_bounds__(256) transpose_half(
    const half* __restrict__ in, half* __restrict__ out,
    int ldin, int ldout, long long sIn, long long sOut)
{
    __shared__ half t[32][34];
    const half* ib = in + (long long)blockIdx.z * sIn;
    half* ob = out + (long long)blockIdx.z * sOut;
    int r0 = blockIdx.y * 32, c0 = blockIdx.x * 32;
    int x = threadIdx.x & 31, y = threadIdx.x >> 5;
#pragma unroll
    for (int j = 0; j < 32; j += 8)
        t[y + j][x] = ib[(long long)(r0 + y + j) * ldin + c0 + x];
    __syncthreads();
#pragma unroll
    for (int j = 0; j < 32; j += 8)
        ob[(long long)(c0 + y + j) * ldout + r0 + x] = t[x][y + j];
}

// ---------------- gw = softmax(q @ W_gp), 64 rows / block --------------------
__global__ void __launch_bounds__(256) gw_kernel2(
    const half* __restrict__ qh, const half* __restrict__ ql,
    const float* __restrict__ Wgp, float* __restrict__ gw)
{
    __shared__ float wt[64][52];
    __shared__ float qt[64][65];
    __shared__ float lg[64][50];
    const int row0 = blockIdx.x * 64;
    const int tid = threadIdx.x;
    const int c  = tid & 63;
    const int rq = tid >> 6;

    float acc[16];
#pragma unroll
    for (int i = 0; i < 16; i++) acc[i] = 0.f;

    for (int kc = 0; kc < DIM / 64; kc++) {
        for (int idx = tid; idx < 64 * GP; idx += 256) {
            int kk = idx / GP, cc = idx - kk * GP;
            wt[kk][cc] = Wgp[(kc * 64 + kk) * GP + cc];
        }
        for (int idx = tid; idx < 4096; idx += 256) {
            int r = idx >> 6, kk = idx & 63;
            long long o = (long long)(row0 + r) * QKVD + kc * 64 + kk;
            qt[r][kk] = __half2float(qh[o]) + __half2float(ql[o]);
        }
        __syncthreads();
        if (c < GP) {
            for (int kk = 0; kk < 64; kk++) {
                float wv = wt[kk][c];
#pragma unroll
                for (int i = 0; i < 16; i++)
                    acc[i] = fmaf(qt[rq * 16 + i][kk], wv, acc[i]);
            }
        }
        __syncthreads();
    }
    if (c < GP)
#pragma unroll
        for (int i = 0; i < 16; i++) lg[rq * 16 + i][c] = acc[i];
    __syncthreads();
    if (tid < 64) {
        float m = lg[tid][0];
        for (int j = 1; j < GP; j++) m = fmaxf(m, lg[tid][j]);
        float s = 0.f;
        float e[GP];
        for (int j = 0; j < GP; j++) { e[j] = expf(lg[tid][j] - m); s += e[j]; }
        float inv = 1.f / s;
        for (int j = 0; j < GP; j++)
            gw[(long long)(row0 + tid) * GP + j] = e[j] * inv;
    }
}

// ---------------- per-row max & sum(exp) over S ------------------------------
__global__ void __launch_bounds__(256) rowstats_kernel(
    const float* __restrict__ S, float* __restrict__ rmax, float* __restrict__ rsum)
{
    const int row = blockIdx.x;
    const float* s = S + (long long)row * SEQ;
    const int tid = threadIdx.x;
    float v[4];
    float mx = -1e30f;
#pragma unroll
    for (int t = 0; t < 4; t++) { v[t] = s[tid + 256 * t]; mx = fmaxf(mx, v[t]); }
    __shared__ float red[256];
    red[tid] = mx; __syncthreads();
    for (int off = 128; off > 0; off >>= 1) {
        if (tid < off) red[tid] = fmaxf(red[tid], red[tid + off]);
        __syncthreads();
    }
    float m = red[0];
    __syncthreads();
    float sum = 0.f;
#pragma unroll
    for (int t = 0; t < 4; t++) sum += expf(v[t] - m);
    red[tid] = sum; __syncthreads();
    for (int off = 128; off > 0; off >>= 1) {
        if (tid < off) red[tid] += red[tid + off];
        __syncthreads();
    }
    if (tid == 0) { rmax[row] = m; rsum[row] = red[0]; }
}

// ------- W = softmax(S) * (a + (1-a)*<gw_i,gw_m>) -> split fp16 --------------
__global__ void __launch_bounds__(256) modulate2(
    const float* __restrict__ S, const float* __restrict__ gw,
    const float* __restrict__ rmax, const float* __restrict__ rsum,
    const float* __restrict__ alpha_p, half* __restrict__ Sh, half* __restrict__ Sl)
{
    __shared__ float gwm[128][51];
    const int b  = blockIdx.z;
    const int i0 = blockIdx.y * 64;
    const int m0 = blockIdx.x * 128;
    const int tid = threadIdx.x;

    for (int idx = tid; idx < 128 * GP; idx += 256) {
        int r = idx / GP, cc = idx - r * GP;
        gwm[r][cc] = gw[(long long)(b * SEQ + m0 + r) * GP + cc];
    }
    __syncthreads();

    const float a = 1.f / (1.f + expf(-alpha_p[0]));
    const float oma = 1.f - a;
    const int ml = tid & 63;
    const int rq = tid >> 6;

    for (int ri = 0; ri < 16; ri++) {
        const int il = ri * 4 + rq;
        const int grow = b * SEQ + i0 + il;
        const float* gp = gw + (long long)grow * GP;
        const float mi  = rmax[grow];
        const float inv = 1.f / rsum[grow];
        const float* srow = S + (long long)grow * SEQ + m0;
        float d0 = 0.f, d1 = 0.f;
#pragma unroll
        for (int cc = 0; cc < GP; cc++) {
            float g = __ldg(gp + cc);
            d0 = fmaf(g, gwm[ml][cc], d0);
            d1 = fmaf(g, gwm[ml + 64][cc], d1);
        }
        float v0 = expf(srow[ml] - mi) * inv * (a + oma * d0);
        float v1 = expf(srow[ml + 64] - mi) * inv * (a + oma * d1);
        long long o = (long long)grow * SEQ + m0;
        half h0 = __float2half_rn(v0), h1 = __float2half_rn(v1);
        Sh[o + ml]      = h0;
        Sh[o + ml + 64] = h1;
        Sl[o + ml]      = __float2half_rn(v0 - __half2float(h0));
        Sl[o + ml + 64] = __float2half_rn(v1 - __half2float(h1));
    }
}

// ---------------- launcher ---------------------------------------------------
extern "C" void kernel_launch(void* const* d_in, const int* in_sizes, int n_in,
                              void* d_out, int out_size)
{
    const float* x      = (const float*)d_in[0];
    const float* W_qkv  = (const float*)d_in[1];
    const float* b_qkv  = (const float*)d_in[2];
    const float* W_proj = (const float*)d_in[3];
    const float* b_proj = (const float*)d_in[4];
    const float* W_gp   = (const float*)d_in[5];
    const float* alpha  = (const float*)d_in[6];
    float* out = (float*)d_out;

    float *gw, *S, *rmax, *rsum;
    half *x_h, *x_l, *qkv_h, *qkv_l, *S_h, *S_l, *Vt_h, *Vt_l, *ov_h, *ov_l;
    half *Wqkvt_h, *Wqkvt_l, *Wprojt_h, *Wprojt_l;
    cudaGetSymbolAddress((void**)&gw,   g_gw);
    cudaGetSymbolAddress((void**)&S,    g_S);
    cudaGetSymbolAddress((void**)&rmax, g_rmax);
    cudaGetSymbolAddress((void**)&rsum, g_rsum);
    cudaGetSymbolAddress((void**)&x_h,  g_x_h);
    cudaGetSymbolAddress((void**)&x_l,  g_x_l);
    cudaGetSymbolAddress((void**)&qkv_h, g_qkv_h);
    cudaGetSymbolAddress((void**)&qkv_l, g_qkv_l);
    cudaGetSymbolAddress((void**)&S_h,  g_S_h);
    cudaGetSymbolAddress((void**)&S_l,  g_S_l);
    cudaGetSymbolAddress((void**)&Vt_h, g_Vt_h);
    cudaGetSymbolAddress((void**)&Vt_l, g_Vt_l);
    cudaGetSymbolAddress((void**)&ov_h, g_ov_h);
    cudaGetSymbolAddress((void**)&ov_l, g_ov_l);
    cudaGetSymbolAddress((void**)&Wqkvt_h,  g_Wqkvt_h);
    cudaGetSymbolAddress((void**)&Wqkvt_l,  g_Wqkvt_l);
    cudaGetSymbolAddress((void**)&Wprojt_h, g_Wprojt_h);
    cudaGetSymbolAddress((void**)&Wprojt_l, g_Wprojt_l);

    const float scale = (float)(1.0 / sqrt((double)DIM));
    cudaFuncSetAttribute(gemm_mma<2,false,true,true>,  cudaFuncAttributeMaxDynamicSharedMemorySize, GSMEM);
    cudaFuncSetAttribute(gemm_mma<2,true,false,false>, cudaFuncAttributeMaxDynamicSharedMemorySize, GSMEM);
    cudaFuncSetAttribute(gemm_mma<2,false,true,false>, cudaFuncAttributeMaxDynamicSharedMemorySize, GSMEM);
    cudaFuncSetAttribute(gemm_mma<2,true,false,true>,  cudaFuncAttributeMaxDynamicSharedMemorySize, GSMEM);

    split_plain<<<(ROWS * DIM) / 1024, 256>>>(x, x_h, x_l, (size_t)ROWS * DIM);
    transpose_split<<<dim3(QKVD / 32, DIM / 32, 1), 256>>>(W_qkv, Wqkvt_h, Wqkvt_l, QKVD, DIM, 0, 0);
    transpose_split<<<dim3(DIM / 32, DIM / 32, 1), 256>>>(W_proj, Wprojt_h, Wprojt_l, DIM, DIM, 0, 0);

    // 1) qkv = x @ W_qkv + b  (2-pass: xh*(Wh+Wl), drops x_l) -> split fp16
    gemm_mma<2,false,true,true><<<dim3(QKVD / 128, ROWS / 128, 1), 256, GSMEM>>>(
        x_h, x_l, DIM, 0, Wqkvt_h, Wqkvt_l, DIM, 0,
        nullptr, qkv_h, qkv_l, QKVD, 0, b_qkv, DIM, 1.0f);

    // 2) gw = softmax(q @ W_gp)
    gw_kernel2<<<ROWS / 64, 256>>>(qkv_h, qkv_l, W_gp, gw);

    // V^T per batch
    transpose_half<<<dim3(DIM / 32, SEQ / 32, BATCH), 256>>>(
        qkv_h + 2 * DIM, Vt_h, QKVD, SEQ, (long long)SEQ * QKVD, (long long)DIM * SEQ);
    transpose_half<<<dim3(DIM / 32, SEQ / 32, BATCH), 256>>>(
        qkv_l + 2 * DIM, Vt_l, QKVD, SEQ, (long long)SEQ * QKVD, (long long)DIM * SEQ);

    // 3) S = scale * Q K^T  (2-pass: Qh*(Kh+Kl), drops Ql)
    gemm_mma<2,true,false,false><<<dim3(SEQ / 128, SEQ / 128, BATCH), 256, GSMEM>>>(
        qkv_h, qkv_l, QKVD, (long long)SEQ * QKVD,
        qkv_h + DIM, qkv_l + DIM, QKVD, (long long)SEQ * QKVD,
        S, nullptr, nullptr, SEQ, (long long)SEQ * SEQ, nullptr, DIM, scale);

    // 4) row stats
    rowstats_kernel<<<ROWS, 256>>>(S, rmax, rsum);

    // 5) modulate -> split fp16 weights
    modulate2<<<dim3(SEQ / 128, SEQ / 64, BATCH), 256>>>(S, gw, rmax, rsum, alpha, S_h, S_l);

    // 6) ov = W @ V  (2-pass: Wh*(Vh+Vl), drops Wl)
    gemm_mma<2,false,true,false><<<dim3(DIM / 128, SEQ / 128, BATCH), 256, GSMEM>>>(
        S_h, S_l, SEQ, (long long)SEQ * SEQ,
        Vt_h, Vt_l, SEQ, (long long)DIM * SEQ,
        nullptr, ov_h, ov_l, DIM, (long long)SEQ * DIM, nullptr, SEQ, 1.0f);

    // 7) out = ov @ W_proj + b  (2-pass: ovh*(Wh+Wl), drops ov_l)
    gemm_mma<2,true,false,true><<<dim3(DIM / 128, ROWS / 128, 1), 256, GSMEM>>>(
        ov_h, ov_l, DIM, 0, Wprojt_h, Wprojt_l, DIM, 0,
        out, nullptr, nullptr, DIM, 0, b_proj, DIM, 1.0f);
}

// round 10
// speedup vs baseline: 1.7607x; 1.0664x over previous
#include <cuda_runtime.h>
#include <cuda_fp16.h>
#include <math.h>
#include <stdint.h>

#define BATCH 16
#define SEQ   1024
#define DIM   768
#define GP    49
#define ROWS  (BATCH * SEQ)      // 16384
#define QKVD  (3 * DIM)          // 2304

// ---------------- scratch (device globals) ----------------------------------
__device__ float g_gw [(size_t)ROWS * GP];
__device__ float g_S  [(size_t)BATCH * SEQ * SEQ];
__device__ float g_rmax[ROWS];
__device__ float g_rsum[ROWS];

__device__ half g_x_h   [(size_t)ROWS * DIM];
__device__ half g_x_l   [(size_t)ROWS * DIM];
__device__ half g_qkv_h [(size_t)ROWS * QKVD];
__device__ half g_qkv_l [(size_t)ROWS * QKVD];
__device__ half g_S_h   [(size_t)BATCH * SEQ * SEQ];
__device__ half g_S_l   [(size_t)BATCH * SEQ * SEQ];
__device__ half g_Vt_h  [(size_t)BATCH * DIM * SEQ];
__device__ half g_Vt_l  [(size_t)BATCH * DIM * SEQ];
__device__ half g_ov_h  [(size_t)ROWS * DIM];
__device__ half g_ov_l  [(size_t)ROWS * DIM];
__device__ half g_Wqkvt_h [(size_t)QKVD * DIM];
__device__ half g_Wqkvt_l [(size_t)QKVD * DIM];
__device__ half g_Wprojt_h[(size_t)DIM * DIM];
__device__ half g_Wprojt_l[(size_t)DIM * DIM];

// ============================ helpers =======================================
__device__ __forceinline__ uint32_t smem_u32(const void* p) {
    uint32_t a;
    asm("{ .reg .u64 t; cvta.to.shared.u64 t, %1; cvt.u32.u64 %0, t; }" : "=r"(a) : "l"(p));
    return a;
}
__device__ __forceinline__ void cp16(uint32_t s, const void* g) {
    asm volatile("cp.async.cg.shared.global [%0], [%1], 16;" :: "r"(s), "l"(g));
}
__device__ __forceinline__ void cp_commit() {
    asm volatile("cp.async.commit_group;" ::: "memory");
}
template<int N>
__device__ __forceinline__ void cp_wait() {
    asm volatile("cp.async.wait_group %0;" :: "n"(N) : "memory");
}
__device__ __forceinline__ void mma16816(float* d, const uint32_t* a, const uint32_t* b) {
    asm volatile(
        "mma.sync.aligned.m16n8k16.row.col.f32.f16.f16.f32 "
        "{%0,%1,%2,%3},{%4,%5,%6,%7},{%8,%9},{%0,%1,%2,%3};"
        : "+f"(d[0]), "+f"(d[1]), "+f"(d[2]), "+f"(d[3])
        : "r"(a[0]), "r"(a[1]), "r"(a[2]), "r"(a[3]), "r"(b[0]), "r"(b[1]));
}
__device__ __forceinline__ void ldmx4(uint32_t& r0, uint32_t& r1, uint32_t& r2, uint32_t& r3,
                                      uint32_t saddr) {
    asm volatile("ldmatrix.sync.aligned.m8n8.x4.shared.b16 {%0,%1,%2,%3}, [%4];"
                 : "=r"(r0), "=r"(r1), "=r"(r2), "=r"(r3) : "r"(saddr));
}
// swizzled byte offset within an 8KB plane (128 logical rows x 4 chunks of 16B)
__device__ __forceinline__ uint32_t swz(int row, int ch) {
    return (uint32_t)(((row >> 1) << 7) |
           (((((row & 1) << 2) + ch) ^ ((row >> 1) & 7)) << 4));
}

// ============== fp16-pair mma.sync GEMM: C = alpha*Ah*(Bh+Bl) (+bias) =======
// 2-pass split (err ~1.9e-4 per GEMM). 128x128 tile, 256 thr, 4-stage ring,
// 3 planes/stage (A_h, B_h, B_l), prefetch depth 3, wait_group<=2.
#define PLANE_B  8192u
#define STAGE_B  24576u
#define NSTAGE   4
#define GSMEM    (NSTAGE * STAGE_B)

template<bool WF32, bool WSPLIT, bool BIAS>
__global__ void __launch_bounds__(256, 2) gemm_mma(
    const half* __restrict__ Ah, int lda, long long strA,
    const half* __restrict__ Bh, const half* __restrict__ Bl, int ldb, long long strB,
    float* __restrict__ C, half* __restrict__ Ch, half* __restrict__ Cl,
    int ldc, long long strC, const float* __restrict__ bias, int K, float alpha)
{
    extern __shared__ __align__(16) char smraw[];
    const uint32_t sb = smem_u32(smraw);
    const int tid  = threadIdx.x;
    const int lane = tid & 31;
    const int w    = tid >> 5;
    const int wm   = w & 1;
    const int wn   = w >> 1;
    const int m0 = blockIdx.y * 128, n0 = blockIdx.x * 128;

    const half* Abh = Ah + (long long)blockIdx.z * strA + (long long)m0 * lda;
    const half* Bbh = Bh + (long long)blockIdx.z * strB + (long long)n0 * ldb;
    const half* Bbl = Bl + (long long)blockIdx.z * strB + (long long)n0 * ldb;

    float acc[4][4][4];
#pragma unroll
    for (int i = 0; i < 4; i++)
#pragma unroll
        for (int j = 0; j < 4; j++)
#pragma unroll
            for (int r = 0; r < 4; r++) acc[i][j][r] = 0.f;

    const int nch = K >> 5;

    // 6 x cp.async(16B)/thread per chunk: planes A_h, B_h, B_l
    auto issue = [&](int k0, int stg) {
        const uint32_t base = sb + (uint32_t)stg * STAGE_B;
#pragma unroll
        for (int i = 0; i < 6; i++) {
            const int plane = i >> 1;
            const int cid = ((i & 1) << 8) + tid;
            const int row = cid >> 2;
            const int ch  = cid & 3;
            const uint32_t so = base + (uint32_t)plane * PLANE_B + swz(row, ch);
            const half* gp;
            if      (plane == 0) gp = Abh + (long long)row * lda + k0 + ch * 8;
            else if (plane == 1) gp = Bbh + (long long)row * ldb + k0 + ch * 8;
            else                 gp = Bbl + (long long)row * ldb + k0 + ch * 8;
            cp16(so, gp);
        }
        cp_commit();
    };

    issue(0, 0);
    issue(32, 1);
    issue(64, 2);

    const int rowl = lane & 15;
    const int cb   = lane >> 4;

    for (int c = 0; c < nch; ++c) {
        const int st = c & (NSTAGE - 1);
        // wait until stage c's group is complete (exact tail counts)
        if      (c < nch - 2) cp_wait<2>();
        else if (c == nch - 2) cp_wait<1>();
        else                   cp_wait<0>();
        __syncthreads();
        if (c + 3 < nch) issue((c + 3) << 5, (c + 3) & (NSTAGE - 1));

        const uint32_t stA_h = sb + (uint32_t)st * STAGE_B;
        const uint32_t stB_h = stA_h + PLANE_B;
        const uint32_t stB_l = stA_h + 2 * PLANE_B;

#pragma unroll
        for (int ks = 0; ks < 2; ks++) {
            const int ch = 2 * ks + cb;
            uint32_t ah[4][4], bh[4][2], bl[4][2];
#pragma unroll
            for (int mi = 0; mi < 4; mi++) {
                int row = wm * 64 + mi * 16 + rowl;
                ldmx4(ah[mi][0], ah[mi][1], ah[mi][2], ah[mi][3], stA_h + swz(row, ch));
            }
#pragma unroll
            for (int p = 0; p < 2; p++) {
                int row = wn * 32 + p * 16 + rowl;
                ldmx4(bh[2*p][0], bh[2*p+1][0], bh[2*p][1], bh[2*p+1][1], stB_h + swz(row, ch));
            }
            // pass 1: Ah*Bh
#pragma unroll
            for (int mi = 0; mi < 4; mi++)
#pragma unroll
                for (int ni = 0; ni < 4; ni++)
                    mma16816(acc[mi][ni], ah[mi], bh[ni]);
            // B-lo loads issued here: latency hides under pass-1 MMA drain
#pragma unroll
            for (int p = 0; p < 2; p++) {
                int row = wn * 32 + p * 16 + rowl;
                ldmx4(bl[2*p][0], bl[2*p+1][0], bl[2*p][1], bl[2*p+1][1], stB_l + swz(row, ch));
            }
            // pass 2: Ah*Bl
#pragma unroll
            for (int mi = 0; mi < 4; mi++)
#pragma unroll
                for (int ni = 0; ni < 4; ni++)
                    mma16816(acc[mi][ni], ah[mi], bl[ni]);
        }
        // single barrier per chunk; 4-stage ring makes stage reuse safe
    }

    float* Cb  = WF32   ? C  + (long long)blockIdx.z * strC : nullptr;
    half*  Chb = WSPLIT ? Ch + (long long)blockIdx.z * strC : nullptr;
    half*  Clb = WSPLIT ? Cl + (long long)blockIdx.z * strC : nullptr;
    const int r0 = m0 + wm * 64 + (lane >> 2);
    const int c0 = n0 + wn * 32 + ((lane & 3) << 1);
#pragma unroll
    for (int mi = 0; mi < 4; mi++) {
#pragma unroll
        for (int ni = 0; ni < 4; ni++) {
            int cc = c0 + ni * 8;
            float bx = 0.f, by = 0.f;
            if (BIAS) { bx = bias[cc]; by = bias[cc + 1]; }
#pragma unroll
            for (int h = 0; h < 2; h++) {
                int rr = r0 + mi * 16 + h * 8;
                float vx = acc[mi][ni][h * 2 + 0] * alpha + bx;
                float vy = acc[mi][ni][h * 2 + 1] * alpha + by;
                long long off = (long long)rr * ldc + cc;
                if (WF32) *(float2*)(Cb + off) = make_float2(vx, vy);
                if (WSPLIT) {
                    half2 hh;
                    hh.x = __float2half_rn(vx); hh.y = __float2half_rn(vy);
                    half2 ll;
                    ll.x = __float2half_rn(vx - __half2float(hh.x));
                    ll.y = __float2half_rn(vy - __half2float(hh.y));
                    *(half2*)(Chb + off) = hh;
                    *(half2*)(Clb + off) = ll;
                }
            }
        }
    }
}

// ================== split fp32 -> (hi, lo) fp16, plain ======================
__global__ void __launch_bounds__(256) split_plain(
    const float* __restrict__ in, half* __restrict__ oh, half* __restrict__ ol, size_t n)
{
    size_t i = ((size_t)blockIdx.x * 256 + threadIdx.x) * 4;
    if (i >= n) return;
    float4 v = *(const float4*)(in + i);
    half2 h0, h1, l0, l1;
    h0.x = __float2half_rn(v.x); h0.y = __float2half_rn(v.y);
    h1.x = __float2half_rn(v.z); h1.y = __float2half_rn(v.w);
    l0.x = __float2half_rn(v.x - __half2float(h0.x));
    l0.y = __float2half_rn(v.y - __half2float(h0.y));
    l1.x = __float2half_rn(v.z - __half2float(h1.x));
    l1.y = __float2half_rn(v.w - __half2float(h1.y));
    *(half2*)(oh + i) = h0; *(half2*)(oh + i + 2) = h1;
    *(half2*)(ol + i) = l0; *(half2*)(ol + i + 2) = l1;
}

// ================== transpose + split fp32 -> fp16 pair =====================
__global__ void __launch_bounds__(256) transpose_split(
    const float* __restrict__ in, half* __restrict__ oh, half* __restrict__ ol,
    int ldin, int ldout, long long sIn, long long sOut)
{
    __shared__ float t[32][33];
    const float* ib = in + (long long)blockIdx.z * sIn;
    half* obh = oh + (long long)blockIdx.z * sOut;
    half* obl = ol + (long long)blockIdx.z * sOut;
    int r0 = blockIdx.y * 32, c0 = blockIdx.x * 32;
    int x = threadIdx.x & 31, y = threadIdx.x >> 5;
#pragma unroll
    for (int j = 0; j < 32; j += 8)
        t[y + j][x] = ib[(long long)(r0 + y + j) * ldin + c0 + x];
    __syncthreads();
#pragma unroll
    for (int j = 0; j < 32; j += 8) {
        float v = t[x][y + j];
        half h = __float2half_rn(v);
        half l = __float2half_rn(v - __half2float(h));
        long long o = (long long)(c0 + y + j) * ldout + r0 + x;
        obh[o] = h; obl[o] = l;
    }
}

// ======= transpose both half planes (V -> V^T), one launch ==================
__global__ void __launch_bounds__(256) transpose_half2(
    const half* __restrict__ inh, const half* __restrict__ inl,
    half* __restrict__ outh, half* __restrict__ outl,
    int ldin, int ldout, long long sIn, long long sOut)
{
    __shared__ half t[2][32][34];
    const half* ibh = inh + (long long)blockIdx.z * sIn;
    const half* ibl = inl + (long long)blockIdx.z * sIn;
    half* obh = outh + (long long)blockIdx.z * sOut;
    half* obl = outl + (long long)blockIdx.z * sOut;
    int r0 = blockIdx.y * 32, c0 = blockIdx.x * 32;
    int x = threadIdx.x & 31, y = threadIdx.x >> 5;
#pragma unroll
    for (int j = 0; j < 32; j += 8) {
        t[0][y + j][x] = ibh[(long long)(r0 + y + j) * ldin + c0 + x];
        t[1][y + j][x] = ibl[(long long)(r0 + y + j) * ldin + c0 + x];
    }
    __syncthreads();
#pragma unroll
    for (int j = 0; j < 32; j += 8) {
        long long o = (long long)(c0 + y + j) * ldout + r0 + x;
        obh[o] = t[0][x][y + j];
        obl[o] = t[1][x][y + j];
    }
}

// ---------------- gw = softmax(q @ W_gp), 64 rows / block --------------------
__global__ void __launch_bounds__(256) gw_kernel2(
    const half* __restrict__ qh, const half* __restrict__ ql,
    const float* __restrict__ Wgp, float* __restrict__ gw)
{
    __shared__ float wt[64][52];
    __shared__ float qt[64][65];
    __shared__ float lg[64][50];
    const int row0 = blockIdx.x * 64;
    const int tid = threadIdx.x;
    const int c  = tid & 63;
    const int rq = tid >> 6;

    float acc[16];
#pragma unroll
    for (int i = 0; i < 16; i++) acc[i] = 0.f;

    for (int kc = 0; kc < DIM / 64; kc++) {
        for (int idx = tid; idx < 64 * GP; idx += 256) {
            int kk = idx / GP, cc = idx - kk * GP;
            wt[kk][cc] = Wgp[(kc * 64 + kk) * GP + cc];
        }
        for (int idx = tid; idx < 4096; idx += 256) {
            int r = idx >> 6, kk = idx & 63;
            long long o = (long long)(row0 + r) * QKVD + kc * 64 + kk;
            qt[r][kk] = __half2float(qh[o]) + __half2float(ql[o]);
        }
        __syncthreads();
        if (c < GP) {
            for (int kk = 0; kk < 64; kk++) {
                float wv = wt[kk][c];
#pragma unroll
                for (int i = 0; i < 16; i++)
                    acc[i] = fmaf(qt[rq * 16 + i][kk], wv, acc[i]);
            }
        }
        __syncthreads();
    }
    if (c < GP)
#pragma unroll
        for (int i = 0; i < 16; i++) lg[rq * 16 + i][c] = acc[i];
    __syncthreads();
    if (tid < 64) {
        float m = lg[tid][0];
        for (int j = 1; j < GP; j++) m = fmaxf(m, lg[tid][j]);
        float s = 0.f;
        float e[GP];
        for (int j = 0; j < GP; j++) { e[j] = expf(lg[tid][j] - m); s += e[j]; }
        float inv = 1.f / s;
        for (int j = 0; j < GP; j++)
            gw[(long long)(row0 + tid) * GP + j] = e[j] * inv;
    }
}

// ---------------- per-row max & sum(exp) over S ------------------------------
__global__ void __launch_bounds__(256) rowstats_kernel(
    const float* __restrict__ S, float* __restrict__ rmax, float* __restrict__ rsum)
{
    const int row = blockIdx.x;
    const float* s = S + (long long)row * SEQ;
    const int tid = threadIdx.x;
    float v[4];
    float mx = -1e30f;
#pragma unroll
    for (int t = 0; t < 4; t++) { v[t] = s[tid + 256 * t]; mx = fmaxf(mx, v[t]); }
    __shared__ float red[256];
    red[tid] = mx; __syncthreads();
    for (int off = 128; off > 0; off >>= 1) {
        if (tid < off) red[tid] = fmaxf(red[tid], red[tid + off]);
        __syncthreads();
    }
    float m = red[0];
    __syncthreads();
    float sum = 0.f;
#pragma unroll
    for (int t = 0; t < 4; t++) sum += expf(v[t] - m);
    red[tid] = sum; __syncthreads();
    for (int off = 128; off > 0; off >>= 1) {
        if (tid < off) red[tid] += red[tid + off];
        __syncthreads();
    }
    if (tid == 0) { rmax[row] = m; rsum[row] = red[0]; }
}

// ------- W = softmax(S) * (a + (1-a)*<gw_i,gw_m>) -> split fp16 --------------
__global__ void __launch_bounds__(256) modulate2(
    const float* __restrict__ S, const float* __restrict__ gw,
    const float* __restrict__ rmax, const float* __restrict__ rsum,
    const float* __restrict__ alpha_p, half* __restrict__ Sh, half* __restrict__ Sl)
{
    __shared__ float gwm[128][51];
    const int b  = blockIdx.z;
    const int i0 = blockIdx.y * 64;
    const int m0 = blockIdx.x * 128;
    const int tid = threadIdx.x;

    for (int idx = tid; idx < 128 * GP; idx += 256) {
        int r = idx / GP, cc = idx - r * GP;
        gwm[r][cc] = gw[(long long)(b * SEQ + m0 + r) * GP + cc];
    }
    __syncthreads();

    const float a = 1.f / (1.f + expf(-alpha_p[0]));
    const float oma = 1.f - a;
    const int ml = tid & 63;
    const int rq = tid >> 6;

    for (int ri = 0; ri < 16; ri++) {
        const int il = ri * 4 + rq;
        const int grow = b * SEQ + i0 + il;
        const float* gp = gw + (long long)grow * GP;
        const float mi  = rmax[grow];
        const float inv = 1.f / rsum[grow];
        const float* srow = S + (long long)grow * SEQ + m0;
        float d0 = 0.f, d1 = 0.f;
#pragma unroll
        for (int cc = 0; cc < GP; cc++) {
            float g = __ldg(gp + cc);
            d0 = fmaf(g, gwm[ml][cc], d0);
            d1 = fmaf(g, gwm[ml + 64][cc], d1);
        }
        float v0 = expf(srow[ml] - mi) * inv * (a + oma * d0);
        float v1 = expf(srow[ml + 64] - mi) * inv * (a + oma * d1);
        long long o = (long long)grow * SEQ + m0;
        half h0 = __float2half_rn(v0), h1 = __float2half_rn(v1);
        Sh[o + ml]      = h0;
        Sh[o + ml + 64] = h1;
        Sl[o + ml]      = __float2half_rn(v0 - __half2float(h0));
        Sl[o + ml + 64] = __float2half_rn(v1 - __half2float(h1));
    }
}

// ---------------- launcher ---------------------------------------------------
extern "C" void kernel_launch(void* const* d_in, const int* in_sizes, int n_in,
                              void* d_out, int out_size)
{
    const float* x      = (const float*)d_in[0];
    const float* W_qkv  = (const float*)d_in[1];
    const float* b_qkv  = (const float*)d_in[2];
    const float* W_proj = (const float*)d_in[3];
    const float* b_proj = (const float*)d_in[4];
    const float* W_gp   = (const float*)d_in[5];
    const float* alpha  = (const float*)d_in[6];
    float* out = (float*)d_out;

    float *gw, *S, *rmax, *rsum;
    half *x_h, *x_l, *qkv_h, *qkv_l, *S_h, *S_l, *Vt_h, *Vt_l, *ov_h, *ov_l;
    half *Wqkvt_h, *Wqkvt_l, *Wprojt_h, *Wprojt_l;
    cudaGetSymbolAddress((void**)&gw,   g_gw);
    cudaGetSymbolAddress((void**)&S,    g_S);
    cudaGetSymbolAddress((void**)&rmax, g_rmax);
    cudaGetSymbolAddress((void**)&rsum, g_rsum);
    cudaGetSymbolAddress((void**)&x_h,  g_x_h);
    cudaGetSymbolAddress((void**)&x_l,  g_x_l);
    cudaGetSymbolAddress((void**)&qkv_h, g_qkv_h);
    cudaGetSymbolAddress((void**)&qkv_l, g_qkv_l);
    cudaGetSymbolAddress((void**)&S_h,  g_S_h);
    cudaGetSymbolAddress((void**)&S_l,  g_S_l);
    cudaGetSymbolAddress((void**)&Vt_h, g_Vt_h);
    cudaGetSymbolAddress((void**)&Vt_l, g_Vt_l);
    cudaGetSymbolAddress((void**)&ov_h, g_ov_h);
    cudaGetSymbolAddress((void**)&ov_l, g_ov_l);
    cudaGetSymbolAddress((void**)&Wqkvt_h,  g_Wqkvt_h);
    cudaGetSymbolAddress((void**)&Wqkvt_l,  g_Wqkvt_l);
    cudaGetSymbolAddress((void**)&Wprojt_h, g_Wprojt_h);
    cudaGetSymbolAddress((void**)&Wprojt_l, g_Wprojt_l);

    const float scale = (float)(1.0 / sqrt((double)DIM));
    cudaFuncSetAttribute(gemm_mma<false,true,true>,  cudaFuncAttributeMaxDynamicSharedMemorySize, GSMEM);
    cudaFuncSetAttribute(gemm_mma<true,false,false>, cudaFuncAttributeMaxDynamicSharedMemorySize, GSMEM);
    cudaFuncSetAttribute(gemm_mma<false,true,false>, cudaFuncAttributeMaxDynamicSharedMemorySize, GSMEM);
    cudaFuncSetAttribute(gemm_mma<true,false,true>,  cudaFuncAttributeMaxDynamicSharedMemorySize, GSMEM);

    split_plain<<<(ROWS * DIM) / 1024, 256>>>(x, x_h, x_l, (size_t)ROWS * DIM);
    transpose_split<<<dim3(QKVD / 32, DIM / 32, 1), 256>>>(W_qkv, Wqkvt_h, Wqkvt_l, QKVD, DIM, 0, 0);
    transpose_split<<<dim3(DIM / 32, DIM / 32, 1), 256>>>(W_proj, Wprojt_h, Wprojt_l, DIM, DIM, 0, 0);

    // 1) qkv = x @ W_qkv + b  (2-pass) -> split fp16
    gemm_mma<false,true,true><<<dim3(QKVD / 128, ROWS / 128, 1), 256, GSMEM>>>(
        x_h, DIM, 0, Wqkvt_h, Wqkvt_l, DIM, 0,
        nullptr, qkv_h, qkv_l, QKVD, 0, b_qkv, DIM, 1.0f);

    // 2) gw = softmax(q @ W_gp)
    gw_kernel2<<<ROWS / 64, 256>>>(qkv_h, qkv_l, W_gp, gw);

    // V^T per batch (both planes in one launch)
    transpose_half2<<<dim3(DIM / 32, SEQ / 32, BATCH), 256>>>(
        qkv_h + 2 * DIM, qkv_l + 2 * DIM, Vt_h, Vt_l,
        QKVD, SEQ, (long long)SEQ * QKVD, (long long)DIM * SEQ);

    // 3) S = scale * Q K^T  (2-pass: Qh*(Kh+Kl))
    gemm_mma<true,false,false><<<dim3(SEQ / 128, SEQ / 128, BATCH), 256, GSMEM>>>(
        qkv_h, QKVD, (long long)SEQ * QKVD,
        qkv_h + DIM, qkv_l + DIM, QKVD, (long long)SEQ * QKVD,
        S, nullptr, nullptr, SEQ, (long long)SEQ * SEQ, nullptr, DIM, scale);

    // 4) row stats
    rowstats_kernel<<<ROWS, 256>>>(S, rmax, rsum);

    // 5) modulate -> split fp16 weights
    modulate2<<<dim3(SEQ / 128, SEQ / 64, BATCH), 256>>>(S, gw, rmax, rsum, alpha, S_h, S_l);

    // 6) ov = W @ V  (2-pass: Wh*(Vh+Vl))
    gemm_mma<false,true,false><<<dim3(DIM / 128, SEQ / 128, BATCH), 256, GSMEM>>>(
        S_h, SEQ, (long long)SEQ * SEQ,
        Vt_h, Vt_l, SEQ, (long long)DIM * SEQ,
        nullptr, ov_h, ov_l, DIM, (long long)SEQ * DIM, nullptr, SEQ, 1.0f);

    // 7) out = ov @ W_proj + b  (2-pass: ovh*(Wh+Wl))
    gemm_mma<true,false,true><<<dim3(DIM / 128, ROWS / 128, 1), 256, GSMEM>>>(
        ov_h, DIM, 0, Wprojt_h, Wprojt_l, DIM, 0,
        out, nullptr, nullptr, DIM, 0, b_proj, DIM, 1.0f);
}

// round 11
// speedup vs baseline: 1.8182x; 1.0326x over previous
#include <cuda_runtime.h>
#include <cuda_fp16.h>
#include <math.h>
#include <stdint.h>

#define BATCH 16
#define SEQ   1024
#define DIM   768
#define GP    49
#define ROWS  (BATCH * SEQ)      // 16384
#define QKVD  (3 * DIM)          // 2304

// ---------------- scratch (device globals) ----------------------------------
__device__ float g_gw [(size_t)ROWS * GP];
__device__ float g_S  [(size_t)BATCH * SEQ * SEQ];
__device__ float g_rmax[ROWS];
__device__ float g_rsum[ROWS];

__device__ half g_x_h   [(size_t)ROWS * DIM];
__device__ half g_qkv_h [(size_t)ROWS * QKVD];
__device__ half g_qkv_l [(size_t)ROWS * QKVD];
__device__ half g_S_h   [(size_t)BATCH * SEQ * SEQ];
__device__ half g_Vt_h  [(size_t)BATCH * DIM * SEQ];
__device__ half g_Vt_l  [(size_t)BATCH * DIM * SEQ];
__device__ half g_ov_h  [(size_t)ROWS * DIM];
__device__ half g_Wqkvt_h [(size_t)QKVD * DIM];
__device__ half g_Wqkvt_l [(size_t)QKVD * DIM];
__device__ half g_Wprojt_h[(size_t)DIM * DIM];
__device__ half g_Wprojt_l[(size_t)DIM * DIM];

// ============================ helpers =======================================
__device__ __forceinline__ uint32_t smem_u32(const void* p) {
    uint32_t a;
    asm("{ .reg .u64 t; cvta.to.shared.u64 t, %1; cvt.u32.u64 %0, t; }" : "=r"(a) : "l"(p));
    return a;
}
__device__ __forceinline__ void cp16(uint32_t s, const void* g) {
    asm volatile("cp.async.cg.shared.global [%0], [%1], 16;" :: "r"(s), "l"(g));
}
__device__ __forceinline__ void cp_commit() {
    asm volatile("cp.async.commit_group;" ::: "memory");
}
template<int N>
__device__ __forceinline__ void cp_wait() {
    asm volatile("cp.async.wait_group %0;" :: "n"(N) : "memory");
}
__device__ __forceinline__ void mma16816(float* d, const uint32_t* a, const uint32_t* b) {
    asm volatile(
        "mma.sync.aligned.m16n8k16.row.col.f32.f16.f16.f32 "
        "{%0,%1,%2,%3},{%4,%5,%6,%7},{%8,%9},{%0,%1,%2,%3};"
        : "+f"(d[0]), "+f"(d[1]), "+f"(d[2]), "+f"(d[3])
        : "r"(a[0]), "r"(a[1]), "r"(a[2]), "r"(a[3]), "r"(b[0]), "r"(b[1]));
}
__device__ __forceinline__ void ldmx4(uint32_t& r0, uint32_t& r1, uint32_t& r2, uint32_t& r3,
                                      uint32_t saddr) {
    asm volatile("ldmatrix.sync.aligned.m8n8.x4.shared.b16 {%0,%1,%2,%3}, [%4];"
                 : "=r"(r0), "=r"(r1), "=r"(r2), "=r"(r3) : "r"(saddr));
}
// swizzled byte offset within an 8KB plane (128 logical rows x 4 chunks of 16B)
__device__ __forceinline__ uint32_t swz(int row, int ch) {
    return (uint32_t)(((row >> 1) << 7) |
           (((((row & 1) << 2) + ch) ^ ((row >> 1) & 7)) << 4));
}

// ============== fp16-pair mma.sync GEMM: C = alpha*Ah*(Bh+Bl) (+bias) =======
// 2-pass split (err ~1.9e-4 per GEMM). 128x128 tile, 256 thr, 4-stage ring,
// 3 planes/stage (A_h, B_h, B_l), prefetch depth 3, wait_group<=2.
#define PLANE_B  8192u
#define STAGE_B  24576u
#define NSTAGE   4
#define GSMEM    (NSTAGE * STAGE_B)

template<bool WF32, bool WHI, bool WLO, bool BIAS>
__global__ void __launch_bounds__(256, 2) gemm_mma(
    const half* __restrict__ Ah, int lda, long long strA,
    const half* __restrict__ Bh, const half* __restrict__ Bl, int ldb, long long strB,
    float* __restrict__ C, half* __restrict__ Ch, half* __restrict__ Cl,
    int ldc, long long strC, const float* __restrict__ bias, int K, float alpha)
{
    extern __shared__ __align__(16) char smraw[];
    const uint32_t sb = smem_u32(smraw);
    const int tid  = threadIdx.x;
    const int lane = tid & 31;
    const int w    = tid >> 5;
    const int wm   = w & 1;
    const int wn   = w >> 1;
    const int m0 = blockIdx.y * 128, n0 = blockIdx.x * 128;

    const half* Abh = Ah + (long long)blockIdx.z * strA + (long long)m0 * lda;
    const half* Bbh = Bh + (long long)blockIdx.z * strB + (long long)n0 * ldb;
    const half* Bbl = Bl + (long long)blockIdx.z * strB + (long long)n0 * ldb;

    float acc[4][4][4];
#pragma unroll
    for (int i = 0; i < 4; i++)
#pragma unroll
        for (int j = 0; j < 4; j++)
#pragma unroll
            for (int r = 0; r < 4; r++) acc[i][j][r] = 0.f;

    const int nch = K >> 5;

    auto issue = [&](int k0, int stg) {
        const uint32_t base = sb + (uint32_t)stg * STAGE_B;
#pragma unroll
        for (int i = 0; i < 6; i++) {
            const int plane = i >> 1;
            const int cid = ((i & 1) << 8) + tid;
            const int row = cid >> 2;
            const int ch  = cid & 3;
            const uint32_t so = base + (uint32_t)plane * PLANE_B + swz(row, ch);
            const half* gp;
            if      (plane == 0) gp = Abh + (long long)row * lda + k0 + ch * 8;
            else if (plane == 1) gp = Bbh + (long long)row * ldb + k0 + ch * 8;
            else                 gp = Bbl + (long long)row * ldb + k0 + ch * 8;
            cp16(so, gp);
        }
        cp_commit();
    };

    issue(0, 0);
    issue(32, 1);
    issue(64, 2);

    const int rowl = lane & 15;
    const int cb   = lane >> 4;

    for (int c = 0; c < nch; ++c) {
        const int st = c & (NSTAGE - 1);
        if      (c < nch - 2) cp_wait<2>();
        else if (c == nch - 2) cp_wait<1>();
        else                   cp_wait<0>();
        __syncthreads();
        if (c + 3 < nch) issue((c + 3) << 5, (c + 3) & (NSTAGE - 1));

        const uint32_t stA_h = sb + (uint32_t)st * STAGE_B;
        const uint32_t stB_h = stA_h + PLANE_B;
        const uint32_t stB_l = stA_h + 2 * PLANE_B;

#pragma unroll
        for (int ks = 0; ks < 2; ks++) {
            const int ch = 2 * ks + cb;
            uint32_t ah[4][4], bh[4][2], bl[4][2];
#pragma unroll
            for (int mi = 0; mi < 4; mi++) {
                int row = wm * 64 + mi * 16 + rowl;
                ldmx4(ah[mi][0], ah[mi][1], ah[mi][2], ah[mi][3], stA_h + swz(row, ch));
            }
#pragma unroll
            for (int p = 0; p < 2; p++) {
                int row = wn * 32 + p * 16 + rowl;
                ldmx4(bh[2*p][0], bh[2*p+1][0], bh[2*p][1], bh[2*p+1][1], stB_h + swz(row, ch));
            }
            // pass 1: Ah*Bh
#pragma unroll
            for (int mi = 0; mi < 4; mi++)
#pragma unroll
                for (int ni = 0; ni < 4; ni++)
                    mma16816(acc[mi][ni], ah[mi], bh[ni]);
            // B-lo loads: latency hides under pass-1 MMA drain
#pragma unroll
            for (int p = 0; p < 2; p++) {
                int row = wn * 32 + p * 16 + rowl;
                ldmx4(bl[2*p][0], bl[2*p+1][0], bl[2*p][1], bl[2*p+1][1], stB_l + swz(row, ch));
            }
            // pass 2: Ah*Bl
#pragma unroll
            for (int mi = 0; mi < 4; mi++)
#pragma unroll
                for (int ni = 0; ni < 4; ni++)
                    mma16816(acc[mi][ni], ah[mi], bl[ni]);
        }
    }

    float* Cb  = WF32 ? C  + (long long)blockIdx.z * strC : nullptr;
    half*  Chb = WHI  ? Ch + (long long)blockIdx.z * strC : nullptr;
    half*  Clb = WLO  ? Cl + (long long)blockIdx.z * strC : nullptr;
    const int r0 = m0 + wm * 64 + (lane >> 2);
    const int c0 = n0 + wn * 32 + ((lane & 3) << 1);
#pragma unroll
    for (int mi = 0; mi < 4; mi++) {
#pragma unroll
        for (int ni = 0; ni < 4; ni++) {
            int cc = c0 + ni * 8;
            float bx = 0.f, by = 0.f;
            if (BIAS) { bx = bias[cc]; by = bias[cc + 1]; }
#pragma unroll
            for (int h = 0; h < 2; h++) {
                int rr = r0 + mi * 16 + h * 8;
                float vx = acc[mi][ni][h * 2 + 0] * alpha + bx;
                float vy = acc[mi][ni][h * 2 + 1] * alpha + by;
                long long off = (long long)rr * ldc + cc;
                if (WF32) *(float2*)(Cb + off) = make_float2(vx, vy);
                if (WHI) {
                    half2 hh;
                    hh.x = __float2half_rn(vx); hh.y = __float2half_rn(vy);
                    *(half2*)(Chb + off) = hh;
                    if (WLO) {
                        half2 ll;
                        ll.x = __float2half_rn(vx - __half2float(hh.x));
                        ll.y = __float2half_rn(vy - __half2float(hh.y));
                        *(half2*)(Clb + off) = ll;
                    }
                }
            }
        }
    }
}

// ================== fp32 -> fp16 hi-only ====================================
__global__ void __launch_bounds__(256) split_hi(
    const float* __restrict__ in, half* __restrict__ oh, size_t n)
{
    size_t i = ((size_t)blockIdx.x * 256 + threadIdx.x) * 4;
    if (i >= n) return;
    float4 v = *(const float4*)(in + i);
    half2 h0, h1;
    h0.x = __float2half_rn(v.x); h0.y = __float2half_rn(v.y);
    h1.x = __float2half_rn(v.z); h1.y = __float2half_rn(v.w);
    *(half2*)(oh + i) = h0; *(half2*)(oh + i + 2) = h1;
}

// ================== transpose + split fp32 -> fp16 pair =====================
__global__ void __launch_bounds__(256) transpose_split(
    const float* __restrict__ in, half* __restrict__ oh, half* __restrict__ ol,
    int ldin, int ldout, long long sIn, long long sOut)
{
    __shared__ float t[32][33];
    const float* ib = in + (long long)blockIdx.z * sIn;
    half* obh = oh + (long long)blockIdx.z * sOut;
    half* obl = ol + (long long)blockIdx.z * sOut;
    int r0 = blockIdx.y * 32, c0 = blockIdx.x * 32;
    int x = threadIdx.x & 31, y = threadIdx.x >> 5;
#pragma unroll
    for (int j = 0; j < 32; j += 8)
        t[y + j][x] = ib[(long long)(r0 + y + j) * ldin + c0 + x];
    __syncthreads();
#pragma unroll
    for (int j = 0; j < 32; j += 8) {
        float v = t[x][y + j];
        half h = __float2half_rn(v);
        half l = __float2half_rn(v - __half2float(h));
        long long o = (long long)(c0 + y + j) * ldout + r0 + x;
        obh[o] = h; obl[o] = l;
    }
}

// ======= transpose both half planes (V -> V^T), one launch ==================
__global__ void __launch_bounds__(256) transpose_half2(
    const half* __restrict__ inh, const half* __restrict__ inl,
    half* __restrict__ outh, half* __restrict__ outl,
    int ldin, int ldout, long long sIn, long long sOut)
{
    __shared__ half t[2][32][34];
    const half* ibh = inh + (long long)blockIdx.z * sIn;
    const half* ibl = inl + (long long)blockIdx.z * sIn;
    half* obh = outh + (long long)blockIdx.z * sOut;
    half* obl = outl + (long long)blockIdx.z * sOut;
    int r0 = blockIdx.y * 32, c0 = blockIdx.x * 32;
    int x = threadIdx.x & 31, y = threadIdx.x >> 5;
#pragma unroll
    for (int j = 0; j < 32; j += 8) {
        t[0][y + j][x] = ibh[(long long)(r0 + y + j) * ldin + c0 + x];
        t[1][y + j][x] = ibl[(long long)(r0 + y + j) * ldin + c0 + x];
    }
    __syncthreads();
#pragma unroll
    for (int j = 0; j < 32; j += 8) {
        long long o = (long long)(c0 + y + j) * ldout + r0 + x;
        obh[o] = t[0][x][y + j];
        obl[o] = t[1][x][y + j];
    }
}

// ---------------- gw = softmax(q @ W_gp), 64 rows / block --------------------
__global__ void __launch_bounds__(256) gw_kernel2(
    const half* __restrict__ qh, const half* __restrict__ ql,
    const float* __restrict__ Wgp, float* __restrict__ gw)
{
    __shared__ float wt[64][52];
    __shared__ float qt[64][65];
    __shared__ float lg[64][50];
    const int row0 = blockIdx.x * 64;
    const int tid = threadIdx.x;
    const int c  = tid & 63;
    const int rq = tid >> 6;

    float acc[16];
#pragma unroll
    for (int i = 0; i < 16; i++) acc[i] = 0.f;

    for (int kc = 0; kc < DIM / 64; kc++) {
        for (int idx = tid; idx < 64 * GP; idx += 256) {
            int kk = idx / GP, cc = idx - kk * GP;
            wt[kk][cc] = Wgp[(kc * 64 + kk) * GP + cc];
        }
        for (int idx = tid; idx < 4096; idx += 256) {
            int r = idx >> 6, kk = idx & 63;
            long long o = (long long)(row0 + r) * QKVD + kc * 64 + kk;
            qt[r][kk] = __half2float(qh[o]) + __half2float(ql[o]);
        }
        __syncthreads();
        if (c < GP) {
            for (int kk = 0; kk < 64; kk++) {
                float wv = wt[kk][c];
#pragma unroll
                for (int i = 0; i < 16; i++)
                    acc[i] = fmaf(qt[rq * 16 + i][kk], wv, acc[i]);
            }
        }
        __syncthreads();
    }
    if (c < GP)
#pragma unroll
        for (int i = 0; i < 16; i++) lg[rq * 16 + i][c] = acc[i];
    __syncthreads();
    if (tid < 64) {
        float m = lg[tid][0];
        for (int j = 1; j < GP; j++) m = fmaxf(m, lg[tid][j]);
        float s = 0.f;
        float e[GP];
        for (int j = 0; j < GP; j++) { e[j] = expf(lg[tid][j] - m); s += e[j]; }
        float inv = 1.f / s;
        for (int j = 0; j < GP; j++)
            gw[(long long)(row0 + tid) * GP + j] = e[j] * inv;
    }
}

// -------- per-row max & sum(exp): warp per row, 8 rows/block -----------------
__global__ void __launch_bounds__(256) rowstats_kernel2(
    const float* __restrict__ S, float* __restrict__ rmax, float* __restrict__ rsum)
{
    const int w    = threadIdx.x >> 5;
    const int lane = threadIdx.x & 31;
    const int row  = blockIdx.x * 8 + w;
    const float4* s4 = (const float4*)(S + (long long)row * SEQ);

    float4 v[8];
    float mx = -1e30f;
#pragma unroll
    for (int i = 0; i < 8; i++) {
        v[i] = s4[i * 32 + lane];
        mx = fmaxf(mx, fmaxf(fmaxf(v[i].x, v[i].y), fmaxf(v[i].z, v[i].w)));
    }
#pragma unroll
    for (int off = 16; off > 0; off >>= 1)
        mx = fmaxf(mx, __shfl_xor_sync(0xffffffffu, mx, off));
    float sum = 0.f;
#pragma unroll
    for (int i = 0; i < 8; i++)
        sum += expf(v[i].x - mx) + expf(v[i].y - mx) + expf(v[i].z - mx) + expf(v[i].w - mx);
#pragma unroll
    for (int off = 16; off > 0; off >>= 1)
        sum += __shfl_xor_sync(0xffffffffu, sum, off);
    if (lane == 0) { rmax[row] = mx; rsum[row] = sum; }
}

// ------- W = softmax(S) * (a + (1-a)*<gw_i,gw_m>) -> fp16 hi only ------------
__global__ void __launch_bounds__(256) modulate2(
    const float* __restrict__ S, const float* __restrict__ gw,
    const float* __restrict__ rmax, const float* __restrict__ rsum,
    const float* __restrict__ alpha_p, half* __restrict__ Sh)
{
    __shared__ float gwm[128][51];
    const int b  = blockIdx.z;
    const int i0 = blockIdx.y * 64;
    const int m0 = blockIdx.x * 128;
    const int tid = threadIdx.x;

    for (int idx = tid; idx < 128 * GP; idx += 256) {
        int r = idx / GP, cc = idx - r * GP;
        gwm[r][cc] = gw[(long long)(b * SEQ + m0 + r) * GP + cc];
    }
    __syncthreads();

    const float a = 1.f / (1.f + expf(-alpha_p[0]));
    const float oma = 1.f - a;
    const int ml = tid & 63;
    const int rq = tid >> 6;

    for (int ri = 0; ri < 16; ri++) {
        const int il = ri * 4 + rq;
        const int grow = b * SEQ + i0 + il;
        const float* gp = gw + (long long)grow * GP;
        const float mi  = rmax[grow];
        const float inv = 1.f / rsum[grow];
        const float* srow = S + (long long)grow * SEQ + m0;
        float d0 = 0.f, d1 = 0.f;
#pragma unroll
        for (int cc = 0; cc < GP; cc++) {
            float g = __ldg(gp + cc);
            d0 = fmaf(g, gwm[ml][cc], d0);
            d1 = fmaf(g, gwm[ml + 64][cc], d1);
        }
        float v0 = expf(srow[ml] - mi) * inv * (a + oma * d0);
        float v1 = expf(srow[ml + 64] - mi) * inv * (a + oma * d1);
        long long o = (long long)grow * SEQ + m0;
        Sh[o + ml]      = __float2half_rn(v0);
        Sh[o + ml + 64] = __float2half_rn(v1);
    }
}

// ---------------- launcher ---------------------------------------------------
extern "C" void kernel_launch(void* const* d_in, const int* in_sizes, int n_in,
                              void* d_out, int out_size)
{
    const float* x      = (const float*)d_in[0];
    const float* W_qkv  = (const float*)d_in[1];
    const float* b_qkv  = (const float*)d_in[2];
    const float* W_proj = (const float*)d_in[3];
    const float* b_proj = (const float*)d_in[4];
    const float* W_gp   = (const float*)d_in[5];
    const float* alpha  = (const float*)d_in[6];
    float* out = (float*)d_out;

    float *gw, *S, *rmax, *rsum;
    half *x_h, *qkv_h, *qkv_l, *S_h, *Vt_h, *Vt_l, *ov_h;
    half *Wqkvt_h, *Wqkvt_l, *Wprojt_h, *Wprojt_l;
    cudaGetSymbolAddress((void**)&gw,   g_gw);
    cudaGetSymbolAddress((void**)&S,    g_S);
    cudaGetSymbolAddress((void**)&rmax, g_rmax);
    cudaGetSymbolAddress((void**)&rsum, g_rsum);
    cudaGetSymbolAddress((void**)&x_h,  g_x_h);
    cudaGetSymbolAddress((void**)&qkv_h, g_qkv_h);
    cudaGetSymbolAddress((void**)&qkv_l, g_qkv_l);
    cudaGetSymbolAddress((void**)&S_h,  g_S_h);
    cudaGetSymbolAddress((void**)&Vt_h, g_Vt_h);
    cudaGetSymbolAddress((void**)&Vt_l, g_Vt_l);
    cudaGetSymbolAddress((void**)&ov_h, g_ov_h);
    cudaGetSymbolAddress((void**)&Wqkvt_h,  g_Wqkvt_h);
    cudaGetSymbolAddress((void**)&Wqkvt_l,  g_Wqkvt_l);
    cudaGetSymbolAddress((void**)&Wprojt_h, g_Wprojt_h);
    cudaGetSymbolAddress((void**)&Wprojt_l, g_Wprojt_l);

    const float scale = (float)(1.0 / sqrt((double)DIM));
    cudaFuncSetAttribute(gemm_mma<false,true,true,true>,   cudaFuncAttributeMaxDynamicSharedMemorySize, GSMEM);
    cudaFuncSetAttribute(gemm_mma<true,false,false,false>, cudaFuncAttributeMaxDynamicSharedMemorySize, GSMEM);
    cudaFuncSetAttribute(gemm_mma<false,true,false,false>, cudaFuncAttributeMaxDynamicSharedMemorySize, GSMEM);
    cudaFuncSetAttribute(gemm_mma<true,false,false,true>,  cudaFuncAttributeMaxDynamicSharedMemorySize, GSMEM);

    split_hi<<<(ROWS * DIM) / 1024, 256>>>(x, x_h, (size_t)ROWS * DIM);
    transpose_split<<<dim3(QKVD / 32, DIM / 32, 1), 256>>>(W_qkv, Wqkvt_h, Wqkvt_l, QKVD, DIM, 0, 0);
    transpose_split<<<dim3(DIM / 32, DIM / 32, 1), 256>>>(W_proj, Wprojt_h, Wprojt_l, DIM, DIM, 0, 0);

    // 1) qkv = x @ W_qkv + b  (2-pass) -> split fp16 (hi + lo)
    gemm_mma<false,true,true,true><<<dim3(QKVD / 128, ROWS / 128, 1), 256, GSMEM>>>(
        x_h, DIM, 0, Wqkvt_h, Wqkvt_l, DIM, 0,
        nullptr, qkv_h, qkv_l, QKVD, 0, b_qkv, DIM, 1.0f);

    // 2) gw = softmax(q @ W_gp)
    gw_kernel2<<<ROWS / 64, 256>>>(qkv_h, qkv_l, W_gp, gw);

    // V^T per batch (both planes, one launch)
    transpose_half2<<<dim3(DIM / 32, SEQ / 32, BATCH), 256>>>(
        qkv_h + 2 * DIM, qkv_l + 2 * DIM, Vt_h, Vt_l,
        QKVD, SEQ, (long long)SEQ * QKVD, (long long)DIM * SEQ);

    // 3) S = scale * Q K^T  (2-pass: Qh*(Kh+Kl)) -> fp32
    gemm_mma<true,false,false,false><<<dim3(SEQ / 128, SEQ / 128, BATCH), 256, GSMEM>>>(
        qkv_h, QKVD, (long long)SEQ * QKVD,
        qkv_h + DIM, qkv_l + DIM, QKVD, (long long)SEQ * QKVD,
        S, nullptr, nullptr, SEQ, (long long)SEQ * SEQ, nullptr, DIM, scale);

    // 4) row stats (warp per row)
    rowstats_kernel2<<<ROWS / 8, 256>>>(S, rmax, rsum);

    // 5) modulate -> fp16 hi only (lo never read by 2-pass ov GEMM)
    modulate2<<<dim3(SEQ / 128, SEQ / 64, BATCH), 256>>>(S, gw, rmax, rsum, alpha, S_h);

    // 6) ov = W @ V  (2-pass: Wh*(Vh+Vl)) -> fp16 hi only
    gemm_mma<false,true,false,false><<<dim3(DIM / 128, SEQ / 128, BATCH), 256, GSMEM>>>(
        S_h, SEQ, (long long)SEQ * SEQ,
        Vt_h, Vt_l, SEQ, (long long)DIM * SEQ,
        nullptr, ov_h, nullptr, DIM, (long long)SEQ * DIM, nullptr, SEQ, 1.0f);

    // 7) out = ov @ W_proj + b  (2-pass: ovh*(Wh+Wl)) -> fp32
    gemm_mma<true,false,false,true><<<dim3(DIM / 128, ROWS / 128, 1), 256, GSMEM>>>(
        ov_h, DIM, 0, Wprojt_h, Wprojt_l, DIM, 0,
        out, nullptr, nullptr, DIM, 0, b_proj, DIM, 1.0f);
}